// round 1
// baseline (speedup 1.0000x reference)
#include <cuda_runtime.h>
#include <math.h>

#define Bc 4
#define Sq 1024
#define Dm 1024
#define Hh 16
#define DHd 64

// Scratch (allocation-free rule: device globals)
__device__ float g_Q[Bc*Hh*Sq*DHd];   // [b*16+h][s][dh], pre-scaled by 1/8
__device__ float g_K[Bc*Hh*Sq*DHd];
__device__ float g_V[Bc*Hh*Sq*DHd];
__device__ float g_A[Bc*Sq*Dm];       // merged-head attention output [b*S+s][h*64+dh]

// ---------------------------------------------------------------------------
// Tiled SGEMM: C = A(MxK) @ B(KxN) + bias
// MODE 0: plain store to C
// MODE 1: QKV scatter into g_Q/g_K/g_V (head-major), Q scaled by 0.125
// MODE 2: A source is g_A (device symbol), plain store to C
// BM=BN=128, BK=16, 256 threads, 8x8 per-thread tile.
// ---------------------------------------------------------------------------
template<int MODE>
__global__ __launch_bounds__(256) void gemm_k(const float* __restrict__ Ain,
                                              const float* __restrict__ B,
                                              const float* __restrict__ bias,
                                              float* __restrict__ C,
                                              int M, int N, int K)
{
    const int BM = 128, BN = 128, BK = 16;
    __shared__ float As[BK][BM];
    __shared__ float Bs[BK][BN];

    const float* A = (MODE == 2) ? (const float*)g_A : Ain;

    int tid  = threadIdx.x;
    int tcol = tid & 15;        // 16 threads across N
    int trow = tid >> 4;        // 16 threads across M
    int mBase = blockIdx.y * BM;
    int nBase = blockIdx.x * BN;

    float acc[8][8];
    #pragma unroll
    for (int i = 0; i < 8; i++)
        #pragma unroll
        for (int j = 0; j < 8; j++) acc[i][j] = 0.f;

    for (int k0 = 0; k0 < K; k0 += BK) {
        // A tile: 128 rows x 16 cols = 512 float4 (transposed into As)
        #pragma unroll
        for (int i = 0; i < 2; i++) {
            int id  = tid + i * 256;
            int row = id >> 2;
            int c4  = (id & 3) * 4;
            float4 v = *(const float4*)(A + (size_t)(mBase + row) * K + k0 + c4);
            As[c4 + 0][row] = v.x;
            As[c4 + 1][row] = v.y;
            As[c4 + 2][row] = v.z;
            As[c4 + 3][row] = v.w;
        }
        // B tile: 16 rows x 128 cols = 512 float4
        #pragma unroll
        for (int i = 0; i < 2; i++) {
            int id  = tid + i * 256;
            int row = id >> 5;
            int c4  = (id & 31) * 4;
            *(float4*)(&Bs[row][c4]) =
                *(const float4*)(B + (size_t)(k0 + row) * N + nBase + c4);
        }
        __syncthreads();

        #pragma unroll
        for (int kk = 0; kk < BK; kk++) {
            float a[8], b[8];
            #pragma unroll
            for (int i = 0; i < 8; i++) a[i] = As[kk][trow * 8 + i];
            #pragma unroll
            for (int j = 0; j < 8; j++) b[j] = Bs[kk][tcol * 8 + j];
            #pragma unroll
            for (int i = 0; i < 8; i++)
                #pragma unroll
                for (int j = 0; j < 8; j++)
                    acc[i][j] += a[i] * b[j];
        }
        __syncthreads();
    }

    // Epilogue
    #pragma unroll
    for (int i = 0; i < 8; i++) {
        int m = mBase + trow * 8 + i;
        #pragma unroll
        for (int j = 0; j < 8; j++) {
            int n = nBase + tcol * 8 + j;
            float v = acc[i][j] + bias[n];
            if (MODE == 1) {
                int which = n >> 10;          // 0=Q, 1=K, 2=V
                int dc = n & 1023;
                int h  = dc >> 6;
                int dh = dc & 63;
                int b  = m >> 10;
                int s  = m & 1023;
                size_t idx = (((size_t)(b * Hh + h)) * Sq + s) * DHd + dh;
                if (which == 0)      g_Q[idx] = v * 0.125f;  // 1/sqrt(64)
                else if (which == 1) g_K[idx] = v;
                else                 g_V[idx] = v;
            } else {
                C[(size_t)m * N + n] = v;
            }
        }
    }
}

// ---------------------------------------------------------------------------
// Causal flash attention, fp32. One thread per query row.
// Block = 128 threads (128 query rows). K/V tiles of 32 in smem.
// Scores staged in smem with stride 33 (conflict-free).
// Grid: (8 q-chunks, 64 b*h)
// ---------------------------------------------------------------------------
__global__ __launch_bounds__(128) void flash_k()
{
    const int TK = 32;
    __shared__ float Ks[TK][DHd];
    __shared__ float Vs[TK][DHd];
    __shared__ float Sc[128][TK + 1];

    int tid = threadIdx.x;
    int bh  = blockIdx.y;          // b*16 + h
    int qc  = blockIdx.x;
    int s   = qc * 128 + tid;      // query row (== sequence position)

    const float* Qb = g_Q + (size_t)bh * Sq * DHd;
    const float* Kb = g_K + (size_t)bh * Sq * DHd;
    const float* Vb = g_V + (size_t)bh * Sq * DHd;

    float q[DHd];
    #pragma unroll
    for (int d = 0; d < DHd; d += 4) {
        float4 v = *(const float4*)(Qb + (size_t)s * DHd + d);
        q[d] = v.x; q[d+1] = v.y; q[d+2] = v.z; q[d+3] = v.w;
    }

    float acc[DHd];
    #pragma unroll
    for (int d = 0; d < DHd; d++) acc[d] = 0.f;
    float mrun = -1e30f, lrun = 0.f;

    int nT = qc * 4 + 4;   // tiles up to and including the diagonal block
    for (int t = 0; t < nT; t++) {
        int ks0 = t * TK;
        // cooperative load of K and V tiles: 512 float4 each pair, 4 per thread
        #pragma unroll
        for (int i = 0; i < 4; i++) {
            int id = tid + i * 128;            // 0..511
            int r  = id >> 4;
            int c  = (id & 15) * 4;
            *(float4*)(&Ks[r][c]) = *(const float4*)(Kb + (size_t)(ks0 + r) * DHd + c);
            *(float4*)(&Vs[r][c]) = *(const float4*)(Vb + (size_t)(ks0 + r) * DHd + c);
        }
        __syncthreads();

        if (ks0 <= s) {
            float tmax = -1e30f;
            for (int j = 0; j < TK; j++) {
                float sc;
                if (ks0 + j <= s) {
                    sc = 0.f;
                    #pragma unroll
                    for (int d = 0; d < DHd; d++) sc += q[d] * Ks[j][d];
                } else {
                    sc = -1e30f;
                }
                Sc[tid][j] = sc;
                tmax = fmaxf(tmax, sc);
            }
            float mnew  = fmaxf(mrun, tmax);
            float scale = __expf(mrun - mnew);
            lrun *= scale;
            #pragma unroll
            for (int d = 0; d < DHd; d++) acc[d] *= scale;
            for (int j = 0; j < TK; j++) {
                float p = __expf(Sc[tid][j] - mnew);
                lrun += p;
                #pragma unroll
                for (int d = 0; d < DHd; d++) acc[d] += p * Vs[j][d];
            }
            mrun = mnew;
        }
        __syncthreads();
    }

    // write merged-head layout: g_A[b*S + s][h*64 + dh]
    int b = bh >> 4, h = bh & 15;
    float inv = 1.f / lrun;
    float* out = g_A + ((size_t)(b * Sq + s)) * Dm + h * DHd;
    #pragma unroll
    for (int d = 0; d < DHd; d += 4) {
        float4 v = make_float4(acc[d] * inv, acc[d+1] * inv,
                               acc[d+2] * inv, acc[d+3] * inv);
        *(float4*)(out + d) = v;
    }
}

// ---------------------------------------------------------------------------
extern "C" void kernel_launch(void* const* d_in, const int* in_sizes, int n_in,
                              void* d_out, int out_size)
{
    (void)in_sizes; (void)n_in; (void)out_size;
    const float* x  = (const float*)d_in[0];   // [4,1024,1024]
    const float* w1 = (const float*)d_in[1];   // [1024,3072]
    const float* b1 = (const float*)d_in[2];   // [3072]
    const float* w2 = (const float*)d_in[3];   // [1024,1024]
    const float* b2 = (const float*)d_in[4];   // [1024]
    float* out = (float*)d_out;                // [4,1024,1024]

    // 1) fused QKV projection + head-major scatter (+ Q pre-scale)
    gemm_k<1><<<dim3(3072/128, 4096/128), 256>>>(x, w1, b1, nullptr, 4096, 3072, 1024);
    // 2) causal attention
    flash_k<<<dim3(8, 64), 128>>>();
    // 3) output projection
    gemm_k<2><<<dim3(1024/128, 4096/128), 256>>>(nullptr, w2, b2, out, 4096, 1024, 1024);
}

// round 3
// speedup vs baseline: 1.6453x; 1.6453x over previous
#include <cuda_runtime.h>
#include <cuda_bf16.h>
#include <cstdint>
#include <math.h>

#define Bc 4
#define Sq 1024
#define Dm 1024
#define Hh 16
#define DHd 64

// ---------------- device scratch (allocation-free rule) ----------------
__device__ float g_Q[Bc*Hh*Sq*DHd];   // [b*16+h][s][dh], pre-scaled by 1/8
__device__ float g_K[Bc*Hh*Sq*DHd];
__device__ float g_V[Bc*Hh*Sq*DHd];
__device__ float g_A[Bc*Sq*Dm];       // attention out, merged heads [b*S+s][d]

// bf16 split operands
__device__ __nv_bfloat16 g_xh[4096*1024], g_xl[4096*1024];     // x  [m][k]
__device__ __nv_bfloat16 g_w1h[3072*1024], g_w1l[3072*1024];   // w1^T [n][k]
__device__ __nv_bfloat16 g_w2h[1024*1024], g_w2l[1024*1024];   // w2^T [n][k]
__device__ __nv_bfloat16 g_ah[4096*1024], g_al[4096*1024];     // attn out [m][k]

// ---------------- helpers ----------------
__device__ __forceinline__ uint32_t smem_u32(const void* p) {
    uint32_t a;
    asm("{ .reg .u64 t; cvta.to.shared.u64 t, %1; cvt.u32.u64 %0, t; }" : "=r"(a) : "l"(p));
    return a;
}
__device__ __forceinline__ void cp_async16(uint32_t saddr, const void* gaddr) {
    asm volatile("cp.async.cg.shared.global [%0], [%1], 16;" :: "r"(saddr), "l"(gaddr));
}
__device__ __forceinline__ void cp_commit() { asm volatile("cp.async.commit_group;" ::: "memory"); }
__device__ __forceinline__ void cp_wait1()  { asm volatile("cp.async.wait_group 1;"  ::: "memory"); }

__device__ __forceinline__ void ldm_x4(uint32_t* r, uint32_t addr) {
    asm volatile("ldmatrix.sync.aligned.m8n8.x4.shared.b16 {%0,%1,%2,%3}, [%4];"
        : "=r"(r[0]), "=r"(r[1]), "=r"(r[2]), "=r"(r[3]) : "r"(addr));
}
__device__ __forceinline__ void mma16816(float* d, const uint32_t* a, const uint32_t* b) {
    asm volatile("mma.sync.aligned.m16n8k16.row.col.f32.bf16.bf16.f32 "
        "{%0,%1,%2,%3}, {%4,%5,%6,%7}, {%8,%9}, {%0,%1,%2,%3};"
        : "+f"(d[0]), "+f"(d[1]), "+f"(d[2]), "+f"(d[3])
        : "r"(a[0]), "r"(a[1]), "r"(a[2]), "r"(a[3]), "r"(b[0]), "r"(b[1]));
}
__device__ __forceinline__ uint32_t swz(uint32_t off) { return off ^ ((off >> 3) & 0x70); }

// ---------------- split conversion kernels ----------------
template<int S>
__global__ void split_k(const float* __restrict__ in, int n)
{
    const float* src = (S == 1) ? (const float*)g_A : in;
    __nv_bfloat16* hi = (S == 1) ? g_ah : g_xh;
    __nv_bfloat16* lo = (S == 1) ? g_al : g_xl;
    int base = (blockIdx.x * blockDim.x + threadIdx.x) * 4;
    if (base >= n) return;
    float4 v = *(const float4*)(src + base);
    float vv[4] = {v.x, v.y, v.z, v.w};
    __nv_bfloat16 h[4], l[4];
    #pragma unroll
    for (int j = 0; j < 4; j++) {
        h[j] = __float2bfloat16(vv[j]);
        l[j] = __float2bfloat16(vv[j] - __bfloat162float(h[j]));
    }
    *(__nv_bfloat162*)(hi + base)     = __nv_bfloat162{h[0], h[1]};
    *(__nv_bfloat162*)(hi + base + 2) = __nv_bfloat162{h[2], h[3]};
    *(__nv_bfloat162*)(lo + base)     = __nv_bfloat162{l[0], l[1]};
    *(__nv_bfloat162*)(lo + base + 2) = __nv_bfloat162{l[2], l[3]};
}

// transpose + split: w[K][N] -> out[n][k]
template<int W>
__global__ void tsplit_k(const float* __restrict__ w)
{
    const int K = 1024;
    const int N = (W == 1) ? 3072 : 1024;
    __nv_bfloat16* th = (W == 1) ? g_w1h : g_w2h;
    __nv_bfloat16* tl = (W == 1) ? g_w1l : g_w2l;
    __shared__ float t[32][33];
    int n0 = blockIdx.x * 32, k0 = blockIdx.y * 32;
    int tx = threadIdx.x, ty = threadIdx.y;   // (32, 8)
    #pragma unroll
    for (int i = 0; i < 32; i += 8)
        t[ty + i][tx] = w[(size_t)(k0 + ty + i) * N + n0 + tx];
    __syncthreads();
    #pragma unroll
    for (int i = 0; i < 32; i += 8) {
        float v = t[tx][ty + i];
        __nv_bfloat16 h = __float2bfloat16(v);
        __nv_bfloat16 l = __float2bfloat16(v - __bfloat162float(h));
        th[(size_t)(n0 + ty + i) * K + k0 + tx] = h;
        tl[(size_t)(n0 + ty + i) * K + k0 + tx] = l;
    }
}

// ---------------- HMMA bf16x3 GEMM ----------------
// Tile 128x128, BK=64, 8 warps (32x64 each), 2-stage cp.async pipeline.
// SMEM per stage: Ah | Al | Bh | Bl, each 128x64 bf16 = 16KB (SW128 swizzled).
static constexpr int ST_BYTES   = 65536;
static constexpr int SMEM_TOTAL = 2 * ST_BYTES;   // 128KB dynamic

__device__ __forceinline__ void load_stage(uint32_t sbase,
                                           const __nv_bfloat16* Ah, const __nv_bfloat16* Al,
                                           const __nv_bfloat16* Bh, const __nv_bfloat16* Bl,
                                           int mBase, int nBase, int K, int k0, int tid)
{
    const __nv_bfloat16* srcs[4] = {Ah, Al, Bh, Bl};
    int rb[4] = {mBase, mBase, nBase, nBase};
    #pragma unroll
    for (int tno = 0; tno < 4; tno++) {
        const char* g = (const char*)(srcs[tno] + (size_t)rb[tno] * K + k0);
        uint32_t sd = sbase + tno * 16384;
        #pragma unroll
        for (int i = 0; i < 4; i++) {
            int id = tid + i * 256;       // 0..1023
            int r  = id >> 3;
            int cb = (id & 7) * 16;
            cp_async16(sd + swz((uint32_t)(r * 128 + cb)), g + (size_t)r * K * 2 + cb);
        }
    }
}

template<int MODE>   // 1 = QKV scatter, 0 = proj store
__global__ __launch_bounds__(256) void tgemm(const float* __restrict__ bias,
                                             float* __restrict__ C)
{
    const int K = 1024;
    const int N = (MODE == 1) ? 3072 : 1024;
    const __nv_bfloat16* Ah = (MODE == 1) ? g_xh : g_ah;
    const __nv_bfloat16* Al = (MODE == 1) ? g_xl : g_al;
    const __nv_bfloat16* Bh = (MODE == 1) ? g_w1h : g_w2h;
    const __nv_bfloat16* Bl = (MODE == 1) ? g_w1l : g_w2l;

    extern __shared__ char smem[];
    uint32_t sb = smem_u32(smem);
    int tid = threadIdx.x;
    int wid = tid >> 5, l = tid & 31;
    int M0 = (wid & 3) * 32;       // warp m offset in tile
    int N0 = (wid >> 2) * 64;      // warp n offset in tile
    int mBase = blockIdx.y * 128, nBase = blockIdx.x * 128;

    float acc[2][8][4];
    #pragma unroll
    for (int mi = 0; mi < 2; mi++)
        #pragma unroll
        for (int nj = 0; nj < 8; nj++)
            #pragma unroll
            for (int k = 0; k < 4; k++) acc[mi][nj][k] = 0.f;

    // precomputed per-lane ldmatrix offsets (within a tile, before k-step shift)
    // A: lanes 0-7 rows0-7/klo, 8-15 rows8-15/klo, 16-23 rows0-7/khi, 24-31 rows8-15/khi
    int aRow = (l & 7) + ((l >> 3) & 1) * 8;
    int aCb  = ((l >> 4) & 1) * 16;
    // B: lanes 0-7 n0-7/klo, 8-15 n0-7/khi, 16-23 n8-15/klo, 24-31 n8-15/khi
    int bRow = (l & 7) + ((l >> 4) & 1) * 8;
    int bCb  = ((l >> 3) & 1) * 16;

    const int NK = K / 64;   // 16
    load_stage(sb,            Ah, Al, Bh, Bl, mBase, nBase, K, 0,  tid); cp_commit();
    load_stage(sb + ST_BYTES, Ah, Al, Bh, Bl, mBase, nBase, K, 64, tid); cp_commit();

    for (int ko = 0; ko < NK; ko++) {
        cp_wait1();
        __syncthreads();
        uint32_t stage = sb + (ko & 1) * ST_BYTES;

        #pragma unroll
        for (int p = 0; p < 3; p++) {
            uint32_t aT = stage + (p == 2 ? 16384 : 0);           // Ah,Ah,Al
            uint32_t bT = stage + 32768 + (p == 1 ? 16384 : 0);   // Bh,Bl,Bh
            #pragma unroll
            for (int ks = 0; ks < 4; ks++) {
                uint32_t ra[2][4];
                #pragma unroll
                for (int mi = 0; mi < 2; mi++)
                    ldm_x4(ra[mi], aT + swz((uint32_t)((M0 + mi*16 + aRow) * 128 + ks*32 + aCb)));
                uint32_t rb4[4][4];
                #pragma unroll
                for (int nq = 0; nq < 4; nq++)
                    ldm_x4(rb4[nq], bT + swz((uint32_t)((N0 + nq*16 + bRow) * 128 + ks*32 + bCb)));
                #pragma unroll
                for (int mi = 0; mi < 2; mi++)
                    #pragma unroll
                    for (int nj = 0; nj < 8; nj++)
                        mma16816(acc[mi][nj], ra[mi], &rb4[nj >> 1][(nj & 1) * 2]);
            }
        }
        __syncthreads();
        if (ko + 2 < NK)
            load_stage(sb + (ko & 1) * ST_BYTES, Ah, Al, Bh, Bl, mBase, nBase, K, (ko + 2) * 64, tid);
        cp_commit();
    }

    // Epilogue: registers -> global (+bias). Lane holds rows (l>>2)+{0,8}, cols (l&3)*2+{0,1}.
    #pragma unroll
    for (int mi = 0; mi < 2; mi++) {
        #pragma unroll
        for (int half = 0; half < 2; half++) {
            int m = mBase + M0 + mi * 16 + (l >> 2) + half * 8;
            #pragma unroll
            for (int nj = 0; nj < 8; nj++) {
                int n = nBase + N0 + nj * 8 + (l & 3) * 2;
                #pragma unroll
                for (int e = 0; e < 2; e++) {
                    float v = acc[mi][nj][half * 2 + e] + bias[n + e];
                    if (MODE == 1) {
                        int nn = n + e;
                        int which = nn >> 10;
                        int dc = nn & 1023;
                        int h = dc >> 6, dh = dc & 63;
                        int b = m >> 10, s2 = m & 1023;
                        size_t gi = (((size_t)(b * Hh + h)) * Sq + s2) * DHd + dh;
                        if (which == 0)      g_Q[gi] = v * 0.125f;
                        else if (which == 1) g_K[gi] = v;
                        else                 g_V[gi] = v;
                    } else {
                        C[(size_t)m * N + n + e] = v;
                    }
                }
            }
        }
    }
}

// ---------------- causal flash attention (unchanged) ----------------
__global__ __launch_bounds__(128) void flash_k()
{
    const int TK = 32;
    __shared__ float Ks[TK][DHd];
    __shared__ float Vs[TK][DHd];
    __shared__ float Sc[128][TK + 1];

    int tid = threadIdx.x;
    int bh  = blockIdx.y;
    int qc  = blockIdx.x;
    int s   = qc * 128 + tid;

    const float* Qb = g_Q + (size_t)bh * Sq * DHd;
    const float* Kb = g_K + (size_t)bh * Sq * DHd;
    const float* Vb = g_V + (size_t)bh * Sq * DHd;

    float q[DHd];
    #pragma unroll
    for (int d = 0; d < DHd; d += 4) {
        float4 v = *(const float4*)(Qb + (size_t)s * DHd + d);
        q[d] = v.x; q[d+1] = v.y; q[d+2] = v.z; q[d+3] = v.w;
    }

    float acc[DHd];
    #pragma unroll
    for (int d = 0; d < DHd; d++) acc[d] = 0.f;
    float mrun = -1e30f, lrun = 0.f;

    int nT = qc * 4 + 4;
    for (int t = 0; t < nT; t++) {
        int ks0 = t * TK;
        #pragma unroll
        for (int i = 0; i < 4; i++) {
            int id = tid + i * 128;
            int r  = id >> 4;
            int c  = (id & 15) * 4;
            *(float4*)(&Ks[r][c]) = *(const float4*)(Kb + (size_t)(ks0 + r) * DHd + c);
            *(float4*)(&Vs[r][c]) = *(const float4*)(Vb + (size_t)(ks0 + r) * DHd + c);
        }
        __syncthreads();

        if (ks0 <= s) {
            float tmax = -1e30f;
            for (int j = 0; j < TK; j++) {
                float sc;
                if (ks0 + j <= s) {
                    sc = 0.f;
                    #pragma unroll
                    for (int d = 0; d < DHd; d++) sc += q[d] * Ks[j][d];
                } else {
                    sc = -1e30f;
                }
                Sc[tid][j] = sc;
                tmax = fmaxf(tmax, sc);
            }
            float mnew  = fmaxf(mrun, tmax);
            float scale = __expf(mrun - mnew);
            lrun *= scale;
            #pragma unroll
            for (int d = 0; d < DHd; d++) acc[d] *= scale;
            for (int j = 0; j < TK; j++) {
                float p = __expf(Sc[tid][j] - mnew);
                lrun += p;
                #pragma unroll
                for (int d = 0; d < DHd; d++) acc[d] += p * Vs[j][d];
            }
            mrun = mnew;
        }
        __syncthreads();
    }

    int b = bh >> 4, h = bh & 15;
    float inv = 1.f / lrun;
    float* out = g_A + ((size_t)(b * Sq + s)) * Dm + h * DHd;
    #pragma unroll
    for (int d = 0; d < DHd; d += 4) {
        float4 v = make_float4(acc[d] * inv, acc[d+1] * inv,
                               acc[d+2] * inv, acc[d+3] * inv);
        *(float4*)(out + d) = v;
    }
}

// ---------------------------------------------------------------------------
extern "C" void kernel_launch(void* const* d_in, const int* in_sizes, int n_in,
                              void* d_out, int out_size)
{
    (void)in_sizes; (void)n_in; (void)out_size;
    const float* x  = (const float*)d_in[0];
    const float* w1 = (const float*)d_in[1];
    const float* b1 = (const float*)d_in[2];
    const float* w2 = (const float*)d_in[3];
    const float* b2 = (const float*)d_in[4];
    float* out = (float*)d_out;

    cudaFuncSetAttribute(tgemm<1>, cudaFuncAttributeMaxDynamicSharedMemorySize, SMEM_TOTAL);
    cudaFuncSetAttribute(tgemm<0>, cudaFuncAttributeMaxDynamicSharedMemorySize, SMEM_TOTAL);

    // split conversions
    split_k<0><<<4096, 256>>>(x, 4096 * 1024);
    tsplit_k<1><<<dim3(3072 / 32, 1024 / 32), dim3(32, 8)>>>(w1);
    tsplit_k<2><<<dim3(1024 / 32, 1024 / 32), dim3(32, 8)>>>(w2);

    // QKV projection on tensor cores (HMMA bf16x3)
    tgemm<1><<<dim3(3072 / 128, 4096 / 128), 256, SMEM_TOTAL>>>(b1, nullptr);

    // causal attention
    flash_k<<<dim3(8, 64), 128>>>();

    // attn-out split + output projection
    split_k<1><<<4096, 256>>>(nullptr, 4096 * 1024);
    tgemm<0><<<dim3(1024 / 128, 4096 / 128), 256, SMEM_TOTAL>>>(b2, out);
}

// round 4
// speedup vs baseline: 3.2341x; 1.9657x over previous
#include <cuda_runtime.h>
#include <cuda_bf16.h>
#include <cstdint>
#include <math.h>

#define Bc 4
#define Sq 1024
#define Dm 1024
#define Hh 16
#define DHd 64

// ---------------- device scratch (allocation-free rule) ----------------
static constexpr size_t NNqkv = (size_t)Bc * Hh * Sq * DHd;   // 4.19M
__device__ __nv_bfloat16 g_Qh[NNqkv], g_Ql[NNqkv];   // [bh][s][dh], Q pre-scaled by 1/8
__device__ __nv_bfloat16 g_Kh[NNqkv], g_Kl[NNqkv];
__device__ __nv_bfloat16 g_Vh[NNqkv], g_Vl[NNqkv];

__device__ __nv_bfloat16 g_xh[4096*1024], g_xl[4096*1024];     // x  [m][k]
__device__ __nv_bfloat16 g_w1h[3072*1024], g_w1l[3072*1024];   // w1^T [n][k]
__device__ __nv_bfloat16 g_w2h[1024*1024], g_w2l[1024*1024];   // w2^T [n][k]
__device__ __nv_bfloat16 g_ah[4096*1024], g_al[4096*1024];     // attn out [m][k]

// ---------------- helpers ----------------
__device__ __forceinline__ uint32_t smem_u32(const void* p) {
    uint32_t a;
    asm("{ .reg .u64 t; cvta.to.shared.u64 t, %1; cvt.u32.u64 %0, t; }" : "=r"(a) : "l"(p));
    return a;
}
__device__ __forceinline__ void cp_async16(uint32_t saddr, const void* gaddr) {
    asm volatile("cp.async.cg.shared.global [%0], [%1], 16;" :: "r"(saddr), "l"(gaddr));
}
__device__ __forceinline__ void cp_commit() { asm volatile("cp.async.commit_group;" ::: "memory"); }
__device__ __forceinline__ void cp_wait1()  { asm volatile("cp.async.wait_group 1;"  ::: "memory"); }
__device__ __forceinline__ void cp_wait0()  { asm volatile("cp.async.wait_group 0;"  ::: "memory"); }

__device__ __forceinline__ void ldm_x4(uint32_t* r, uint32_t addr) {
    asm volatile("ldmatrix.sync.aligned.m8n8.x4.shared.b16 {%0,%1,%2,%3}, [%4];"
        : "=r"(r[0]), "=r"(r[1]), "=r"(r[2]), "=r"(r[3]) : "r"(addr));
}
__device__ __forceinline__ void ldm_x4_t(uint32_t* r, uint32_t addr) {
    asm volatile("ldmatrix.sync.aligned.m8n8.x4.trans.shared.b16 {%0,%1,%2,%3}, [%4];"
        : "=r"(r[0]), "=r"(r[1]), "=r"(r[2]), "=r"(r[3]) : "r"(addr));
}
__device__ __forceinline__ void mma16816(float* d, const uint32_t* a, const uint32_t* b) {
    asm volatile("mma.sync.aligned.m16n8k16.row.col.f32.bf16.bf16.f32 "
        "{%0,%1,%2,%3}, {%4,%5,%6,%7}, {%8,%9}, {%0,%1,%2,%3};"
        : "+f"(d[0]), "+f"(d[1]), "+f"(d[2]), "+f"(d[3])
        : "r"(a[0]), "r"(a[1]), "r"(a[2]), "r"(a[3]), "r"(b[0]), "r"(b[1]));
}
__device__ __forceinline__ uint32_t swz(uint32_t off) { return off ^ ((off >> 3) & 0x70); }

__device__ __forceinline__ void pack_hl(float a, float b, uint32_t& hi, uint32_t& lo) {
    __nv_bfloat162 hh = __floats2bfloat162_rn(a, b);
    float ra = a - __bfloat162float(hh.x);
    float rb = b - __bfloat162float(hh.y);
    __nv_bfloat162 ll = __floats2bfloat162_rn(ra, rb);
    hi = *reinterpret_cast<uint32_t*>(&hh);
    lo = *reinterpret_cast<uint32_t*>(&ll);
}

// ---------------- split conversion kernels ----------------
__global__ void split_k(const float* __restrict__ in, int n)
{
    int base = (blockIdx.x * blockDim.x + threadIdx.x) * 4;
    if (base >= n) return;
    float4 v = *(const float4*)(in + base);
    float vv[4] = {v.x, v.y, v.z, v.w};
    __nv_bfloat16 h[4], l[4];
    #pragma unroll
    for (int j = 0; j < 4; j++) {
        h[j] = __float2bfloat16(vv[j]);
        l[j] = __float2bfloat16(vv[j] - __bfloat162float(h[j]));
    }
    *(__nv_bfloat162*)(g_xh + base)     = __nv_bfloat162{h[0], h[1]};
    *(__nv_bfloat162*)(g_xh + base + 2) = __nv_bfloat162{h[2], h[3]};
    *(__nv_bfloat162*)(g_xl + base)     = __nv_bfloat162{l[0], l[1]};
    *(__nv_bfloat162*)(g_xl + base + 2) = __nv_bfloat162{l[2], l[3]};
}

template<int W>
__global__ void tsplit_k(const float* __restrict__ w)
{
    const int K = 1024;
    const int N = (W == 1) ? 3072 : 1024;
    __nv_bfloat16* th = (W == 1) ? g_w1h : g_w2h;
    __nv_bfloat16* tl = (W == 1) ? g_w1l : g_w2l;
    __shared__ float t[32][33];
    int n0 = blockIdx.x * 32, k0 = blockIdx.y * 32;
    int tx = threadIdx.x, ty = threadIdx.y;
    #pragma unroll
    for (int i = 0; i < 32; i += 8)
        t[ty + i][tx] = w[(size_t)(k0 + ty + i) * N + n0 + tx];
    __syncthreads();
    #pragma unroll
    for (int i = 0; i < 32; i += 8) {
        float v = t[tx][ty + i];
        __nv_bfloat16 h = __float2bfloat16(v);
        __nv_bfloat16 l = __float2bfloat16(v - __bfloat162float(h));
        th[(size_t)(n0 + ty + i) * K + k0 + tx] = h;
        tl[(size_t)(n0 + ty + i) * K + k0 + tx] = l;
    }
}

// ---------------- HMMA bf16x3 GEMM ----------------
static constexpr int ST_BYTES   = 65536;
static constexpr int SMEM_TOTAL = 2 * ST_BYTES;

__device__ __forceinline__ void load_stage(uint32_t sbase,
                                           const __nv_bfloat16* Ah, const __nv_bfloat16* Al,
                                           const __nv_bfloat16* Bh, const __nv_bfloat16* Bl,
                                           int mBase, int nBase, int K, int k0, int tid)
{
    const __nv_bfloat16* srcs[4] = {Ah, Al, Bh, Bl};
    int rb[4] = {mBase, mBase, nBase, nBase};
    #pragma unroll
    for (int tno = 0; tno < 4; tno++) {
        const char* g = (const char*)(srcs[tno] + (size_t)rb[tno] * K + k0);
        uint32_t sd = sbase + tno * 16384;
        #pragma unroll
        for (int i = 0; i < 4; i++) {
            int id = tid + i * 256;
            int r  = id >> 3;
            int cb = (id & 7) * 16;
            cp_async16(sd + swz((uint32_t)(r * 128 + cb)), g + (size_t)r * K * 2 + cb);
        }
    }
}

template<int MODE>   // 1 = QKV scatter (bf16 hi/lo), 0 = proj store fp32
__global__ __launch_bounds__(256) void tgemm(const float* __restrict__ bias,
                                             float* __restrict__ C)
{
    const int K = 1024;
    const int N = (MODE == 1) ? 3072 : 1024;
    const __nv_bfloat16* Ah = (MODE == 1) ? g_xh : g_ah;
    const __nv_bfloat16* Al = (MODE == 1) ? g_xl : g_al;
    const __nv_bfloat16* Bh = (MODE == 1) ? g_w1h : g_w2h;
    const __nv_bfloat16* Bl = (MODE == 1) ? g_w1l : g_w2l;

    extern __shared__ char smem[];
    uint32_t sb = smem_u32(smem);
    int tid = threadIdx.x;
    int wid = tid >> 5, l = tid & 31;
    int M0 = (wid & 3) * 32;
    int N0 = (wid >> 2) * 64;
    int mBase = blockIdx.y * 128, nBase = blockIdx.x * 128;

    float acc[2][8][4];
    #pragma unroll
    for (int mi = 0; mi < 2; mi++)
        #pragma unroll
        for (int nj = 0; nj < 8; nj++)
            #pragma unroll
            for (int k = 0; k < 4; k++) acc[mi][nj][k] = 0.f;

    int aRow = (l & 7) + ((l >> 3) & 1) * 8;
    int aCb  = ((l >> 4) & 1) * 16;
    int bRow = (l & 7) + ((l >> 4) & 1) * 8;
    int bCb  = ((l >> 3) & 1) * 16;

    const int NK = K / 64;
    load_stage(sb,            Ah, Al, Bh, Bl, mBase, nBase, K, 0,  tid); cp_commit();
    load_stage(sb + ST_BYTES, Ah, Al, Bh, Bl, mBase, nBase, K, 64, tid); cp_commit();

    for (int ko = 0; ko < NK; ko++) {
        cp_wait1();
        __syncthreads();
        uint32_t stage = sb + (ko & 1) * ST_BYTES;

        #pragma unroll
        for (int p = 0; p < 3; p++) {
            uint32_t aT = stage + (p == 2 ? 16384 : 0);
            uint32_t bT = stage + 32768 + (p == 1 ? 16384 : 0);
            #pragma unroll
            for (int ks = 0; ks < 4; ks++) {
                uint32_t ra[2][4];
                #pragma unroll
                for (int mi = 0; mi < 2; mi++)
                    ldm_x4(ra[mi], aT + swz((uint32_t)((M0 + mi*16 + aRow) * 128 + ks*32 + aCb)));
                uint32_t rb4[4][4];
                #pragma unroll
                for (int nq = 0; nq < 4; nq++)
                    ldm_x4(rb4[nq], bT + swz((uint32_t)((N0 + nq*16 + bRow) * 128 + ks*32 + bCb)));
                #pragma unroll
                for (int mi = 0; mi < 2; mi++)
                    #pragma unroll
                    for (int nj = 0; nj < 8; nj++)
                        mma16816(acc[mi][nj], ra[mi], &rb4[nj >> 1][(nj & 1) * 2]);
            }
        }
        __syncthreads();
        if (ko + 2 < NK)
            load_stage(sb + (ko & 1) * ST_BYTES, Ah, Al, Bh, Bl, mBase, nBase, K, (ko + 2) * 64, tid);
        cp_commit();
    }

    #pragma unroll
    for (int mi = 0; mi < 2; mi++) {
        #pragma unroll
        for (int half = 0; half < 2; half++) {
            int m = mBase + M0 + mi * 16 + (l >> 2) + half * 8;
            #pragma unroll
            for (int nj = 0; nj < 8; nj++) {
                int n = nBase + N0 + nj * 8 + (l & 3) * 2;
                float v0 = acc[mi][nj][half * 2 + 0] + bias[n];
                float v1 = acc[mi][nj][half * 2 + 1] + bias[n + 1];
                if (MODE == 1) {
                    int which = n >> 10;
                    int dc = n & 1023;
                    int h = dc >> 6, dh = dc & 63;
                    int b = m >> 10, s2 = m & 1023;
                    size_t gi = (((size_t)(b * Hh + h)) * Sq + s2) * DHd + dh;
                    if (which == 0) { v0 *= 0.125f; v1 *= 0.125f; }
                    uint32_t hh, ll;
                    pack_hl(v0, v1, hh, ll);
                    if (which == 0)      { *(uint32_t*)&g_Qh[gi] = hh; *(uint32_t*)&g_Ql[gi] = ll; }
                    else if (which == 1) { *(uint32_t*)&g_Kh[gi] = hh; *(uint32_t*)&g_Kl[gi] = ll; }
                    else                 { *(uint32_t*)&g_Vh[gi] = hh; *(uint32_t*)&g_Vl[gi] = ll; }
                } else {
                    C[(size_t)m * N + n]     = v0;
                    C[(size_t)m * N + n + 1] = v1;
                }
            }
        }
    }
}

// ---------------- tensor-core causal flash attention ----------------
// SMEM: Qh[0,16K) Ql[16K,32K) ; stages at 32K: per stage {Kh,Kl,Vh,Vl} x 8KB
static constexpr int FL_SMEM = 32768 + 2 * 32768;

__device__ __forceinline__ void load_kv(uint32_t sdst, int bh, int kt, int tid)
{
    const __nv_bfloat16* srcs[4] = {g_Kh, g_Kl, g_Vh, g_Vl};
    size_t base = (size_t)bh * Sq * DHd + (size_t)kt * 64 * DHd;
    #pragma unroll
    for (int t = 0; t < 4; t++) {
        const char* g = (const char*)(srcs[t] + base);
        uint32_t sd = sdst + t * 8192;
        #pragma unroll
        for (int i = 0; i < 2; i++) {
            int id = tid + i * 256;        // 0..511
            int r  = id >> 3;
            int cb = (id & 7) * 16;
            cp_async16(sd + swz((uint32_t)(r * 128 + cb)), g + (size_t)r * 128 + cb);
        }
    }
}

__global__ __launch_bounds__(256) void flash_mma()
{
    extern __shared__ char smem[];
    uint32_t sb = smem_u32(smem);
    int tid = threadIdx.x;
    int w = tid >> 5, l = tid & 31;

    // schedule longest q-chunks first
    int qc = 7 - (blockIdx.x >> 6);
    int bh = blockIdx.x & 63;
    int qBase = qc * 128;

    // load Q tile (hi+lo), 128 rows x 128B each
    {
        const char* gh = (const char*)(g_Qh + (size_t)bh * Sq * DHd + (size_t)qBase * DHd);
        const char* gl = (const char*)(g_Ql + (size_t)bh * Sq * DHd + (size_t)qBase * DHd);
        #pragma unroll
        for (int i = 0; i < 4; i++) {
            int id = tid + i * 256;        // 0..1023
            int r  = id >> 3;
            int cb = (id & 7) * 16;
            cp_async16(sb +         swz((uint32_t)(r * 128 + cb)), gh + (size_t)r * 128 + cb);
            cp_async16(sb + 16384 + swz((uint32_t)(r * 128 + cb)), gl + (size_t)r * 128 + cb);
        }
    }
    load_kv(sb + 32768, bh, 0, tid);
    cp_commit();                                   // group0: Q + tile0
    int nT = (qc + 1) * 2;
    load_kv(sb + 32768 + 32768, bh, 1, tid);
    cp_commit();                                   // group1: tile1

    cp_wait1();                                    // Q + tile0 done
    __syncthreads();

    int aRow = (l & 7) + ((l >> 3) & 1) * 8;
    int aCb  = ((l >> 4) & 1) * 16;
    int bRow = (l & 7) + ((l >> 4) & 1) * 8;
    int bCb  = ((l >> 3) & 1) * 16;
    // V (trans) addressing
    int vRow = (l & 7) + ((l >> 3) & 1) * 8;
    int vCb  = ((l >> 4) & 1) * 16;

    uint32_t qh[4][4], ql[4][4];
    #pragma unroll
    for (int ks = 0; ks < 4; ks++) {
        ldm_x4(qh[ks], sb +         swz((uint32_t)((w*16 + aRow) * 128 + ks*32 + aCb)));
        ldm_x4(ql[ks], sb + 16384 + swz((uint32_t)((w*16 + aRow) * 128 + ks*32 + aCb)));
    }

    float o[8][4];
    #pragma unroll
    for (int nj = 0; nj < 8; nj++)
        #pragma unroll
        for (int k = 0; k < 4; k++) o[nj][k] = 0.f;
    float m0 = -1e30f, m1 = -1e30f, l0 = 0.f, l1 = 0.f;

    for (int kt = 0; kt < nT; kt++) {
        cp_wait1();
        __syncthreads();
        uint32_t stage = sb + 32768 + (kt & 1) * 32768;

        bool skip = (kt * 64 > qBase + w * 16 + 15);
        if (!skip) {
            // ---- S = Q K^T (3 passes) ----
            float sacc[8][4];
            #pragma unroll
            for (int nj = 0; nj < 8; nj++)
                #pragma unroll
                for (int k = 0; k < 4; k++) sacc[nj][k] = 0.f;

            #pragma unroll
            for (int ks = 0; ks < 4; ks++) {
                #pragma unroll
                for (int nq = 0; nq < 4; nq++) {
                    uint32_t kh4[4], kl4[4];
                    ldm_x4(kh4, stage +        swz((uint32_t)((nq*16 + bRow) * 128 + ks*32 + bCb)));
                    ldm_x4(kl4, stage + 8192 + swz((uint32_t)((nq*16 + bRow) * 128 + ks*32 + bCb)));
                    mma16816(sacc[2*nq],   qh[ks], &kh4[0]);
                    mma16816(sacc[2*nq+1], qh[ks], &kh4[2]);
                    mma16816(sacc[2*nq],   qh[ks], &kl4[0]);
                    mma16816(sacc[2*nq+1], qh[ks], &kl4[2]);
                    mma16816(sacc[2*nq],   ql[ks], &kh4[0]);
                    mma16816(sacc[2*nq+1], ql[ks], &kh4[2]);
                }
            }

            // ---- causal mask ----
            int r0 = qBase + w * 16 + (l >> 2);
            if (kt * 64 + 63 > r0) {
                int kc = kt * 64 + (l & 3) * 2;
                #pragma unroll
                for (int nj = 0; nj < 8; nj++) {
                    int k0 = kc + nj * 8;
                    if (k0     > r0)     sacc[nj][0] = -1e30f;
                    if (k0 + 1 > r0)     sacc[nj][1] = -1e30f;
                    if (k0     > r0 + 8) sacc[nj][2] = -1e30f;
                    if (k0 + 1 > r0 + 8) sacc[nj][3] = -1e30f;
                }
            }

            // ---- online softmax ----
            float mx0 = -1e30f, mx1 = -1e30f;
            #pragma unroll
            for (int nj = 0; nj < 8; nj++) {
                mx0 = fmaxf(mx0, fmaxf(sacc[nj][0], sacc[nj][1]));
                mx1 = fmaxf(mx1, fmaxf(sacc[nj][2], sacc[nj][3]));
            }
            mx0 = fmaxf(mx0, __shfl_xor_sync(0xffffffffu, mx0, 1));
            mx0 = fmaxf(mx0, __shfl_xor_sync(0xffffffffu, mx0, 2));
            mx1 = fmaxf(mx1, __shfl_xor_sync(0xffffffffu, mx1, 1));
            mx1 = fmaxf(mx1, __shfl_xor_sync(0xffffffffu, mx1, 2));
            float mn0 = fmaxf(m0, mx0), mn1 = fmaxf(m1, mx1);
            float sc0 = __expf(m0 - mn0), sc1 = __expf(m1 - mn1);
            l0 *= sc0; l1 *= sc1;
            #pragma unroll
            for (int nj = 0; nj < 8; nj++) {
                o[nj][0] *= sc0; o[nj][1] *= sc0;
                o[nj][2] *= sc1; o[nj][3] *= sc1;
            }
            #pragma unroll
            for (int nj = 0; nj < 8; nj++) {
                sacc[nj][0] = __expf(sacc[nj][0] - mn0); l0 += sacc[nj][0];
                sacc[nj][1] = __expf(sacc[nj][1] - mn0); l0 += sacc[nj][1];
                sacc[nj][2] = __expf(sacc[nj][2] - mn1); l1 += sacc[nj][2];
                sacc[nj][3] = __expf(sacc[nj][3] - mn1); l1 += sacc[nj][3];
            }
            m0 = mn0; m1 = mn1;

            // ---- P -> bf16 hi/lo A-frags (C-layout == A-layout identity) ----
            uint32_t pah[4][4], pal[4][4];
            #pragma unroll
            for (int ks = 0; ks < 4; ks++) {
                pack_hl(sacc[2*ks][0],   sacc[2*ks][1],   pah[ks][0], pal[ks][0]);
                pack_hl(sacc[2*ks][2],   sacc[2*ks][3],   pah[ks][1], pal[ks][1]);
                pack_hl(sacc[2*ks+1][0], sacc[2*ks+1][1], pah[ks][2], pal[ks][2]);
                pack_hl(sacc[2*ks+1][2], sacc[2*ks+1][3], pah[ks][3], pal[ks][3]);
            }

            // ---- O += P V (3 passes) ----
            uint32_t vStage = stage + 16384;
            #pragma unroll
            for (int ks = 0; ks < 4; ks++) {
                #pragma unroll
                for (int nq = 0; nq < 4; nq++) {
                    uint32_t vh4[4], vl4[4];
                    ldm_x4_t(vh4, vStage +        swz((uint32_t)((ks*16 + vRow) * 128 + nq*32 + vCb)));
                    ldm_x4_t(vl4, vStage + 8192 + swz((uint32_t)((ks*16 + vRow) * 128 + nq*32 + vCb)));
                    mma16816(o[2*nq],   pah[ks], &vh4[0]);
                    mma16816(o[2*nq+1], pah[ks], &vh4[2]);
                    mma16816(o[2*nq],   pah[ks], &vl4[0]);
                    mma16816(o[2*nq+1], pah[ks], &vl4[2]);
                    mma16816(o[2*nq],   pal[ks], &vh4[0]);
                    mma16816(o[2*nq+1], pal[ks], &vh4[2]);
                }
            }
        }

        __syncthreads();
        if (kt + 2 < nT) load_kv(sb + 32768 + (kt & 1) * 32768, bh, kt + 2, tid);
        cp_commit();
    }
    cp_wait0();

    // ---- epilogue ----
    l0 += __shfl_xor_sync(0xffffffffu, l0, 1);
    l0 += __shfl_xor_sync(0xffffffffu, l0, 2);
    l1 += __shfl_xor_sync(0xffffffffu, l1, 1);
    l1 += __shfl_xor_sync(0xffffffffu, l1, 2);
    float inv0 = 1.f / l0, inv1 = 1.f / l1;

    int b = bh >> 4, h = bh & 15;
    int row0 = qBase + w * 16 + (l >> 2);
    #pragma unroll
    for (int half = 0; half < 2; half++) {
        int row = row0 + half * 8;
        float inv = half ? inv1 : inv0;
        #pragma unroll
        for (int nj = 0; nj < 8; nj++) {
            int col = h * 64 + nj * 8 + (l & 3) * 2;
            float v0 = o[nj][half * 2 + 0] * inv;
            float v1 = o[nj][half * 2 + 1] * inv;
            uint32_t hh, ll;
            pack_hl(v0, v1, hh, ll);
            size_t gi = (size_t)(b * Sq + row) * Dm + col;
            *(uint32_t*)&g_ah[gi] = hh;
            *(uint32_t*)&g_al[gi] = ll;
        }
    }
}

// ---------------------------------------------------------------------------
extern "C" void kernel_launch(void* const* d_in, const int* in_sizes, int n_in,
                              void* d_out, int out_size)
{
    (void)in_sizes; (void)n_in; (void)out_size;
    const float* x  = (const float*)d_in[0];
    const float* w1 = (const float*)d_in[1];
    const float* b1 = (const float*)d_in[2];
    const float* w2 = (const float*)d_in[3];
    const float* b2 = (const float*)d_in[4];
    float* out = (float*)d_out;

    cudaFuncSetAttribute(tgemm<1>, cudaFuncAttributeMaxDynamicSharedMemorySize, SMEM_TOTAL);
    cudaFuncSetAttribute(tgemm<0>, cudaFuncAttributeMaxDynamicSharedMemorySize, SMEM_TOTAL);
    cudaFuncSetAttribute(flash_mma, cudaFuncAttributeMaxDynamicSharedMemorySize, FL_SMEM);

    split_k<<<4096, 256>>>(x, 4096 * 1024);
    tsplit_k<1><<<dim3(3072 / 32, 1024 / 32), dim3(32, 8)>>>(w1);
    tsplit_k<2><<<dim3(1024 / 32, 1024 / 32), dim3(32, 8)>>>(w2);

    tgemm<1><<<dim3(3072 / 128, 4096 / 128), 256, SMEM_TOTAL>>>(b1, nullptr);
    flash_mma<<<512, 256, FL_SMEM>>>();
    tgemm<0><<<dim3(1024 / 128, 4096 / 128), 256, SMEM_TOTAL>>>(b2, out);
}

// round 5
// speedup vs baseline: 3.5801x; 1.1070x over previous
#include <cuda_runtime.h>
#include <cuda_bf16.h>
#include <cstdint>
#include <math.h>

#define Bc 4
#define Sq 1024
#define Dm 1024
#define Hh 16
#define DHd 64

// ---------------- device scratch (allocation-free rule) ----------------
static constexpr size_t NNqkv = (size_t)Bc * Hh * Sq * DHd;
__device__ __nv_bfloat16 g_Qh[NNqkv], g_Ql[NNqkv];   // Q pre-scaled by 1/8
__device__ __nv_bfloat16 g_Kh[NNqkv], g_Kl[NNqkv];
__device__ __nv_bfloat16 g_Vh[NNqkv], g_Vl[NNqkv];

__device__ __nv_bfloat16 g_xh[4096*1024], g_xl[4096*1024];
__device__ __nv_bfloat16 g_w1h[3072*1024], g_w1l[3072*1024];
__device__ __nv_bfloat16 g_w2h[1024*1024], g_w2l[1024*1024];
__device__ __nv_bfloat16 g_ah[4096*1024], g_al[4096*1024];

// ---------------- helpers ----------------
__device__ __forceinline__ uint32_t smem_u32(const void* p) {
    uint32_t a;
    asm("{ .reg .u64 t; cvta.to.shared.u64 t, %1; cvt.u32.u64 %0, t; }" : "=r"(a) : "l"(p));
    return a;
}
__device__ __forceinline__ void cp_async16(uint32_t saddr, const void* gaddr) {
    asm volatile("cp.async.cg.shared.global [%0], [%1], 16;" :: "r"(saddr), "l"(gaddr));
}
__device__ __forceinline__ void cp_commit() { asm volatile("cp.async.commit_group;" ::: "memory"); }
__device__ __forceinline__ void cp_wait1()  { asm volatile("cp.async.wait_group 1;"  ::: "memory"); }
__device__ __forceinline__ void cp_wait0()  { asm volatile("cp.async.wait_group 0;"  ::: "memory"); }

__device__ __forceinline__ void ldm_x4(uint32_t* r, uint32_t addr) {
    asm volatile("ldmatrix.sync.aligned.m8n8.x4.shared.b16 {%0,%1,%2,%3}, [%4];"
        : "=r"(r[0]), "=r"(r[1]), "=r"(r[2]), "=r"(r[3]) : "r"(addr));
}
__device__ __forceinline__ void ldm_x4_t(uint32_t* r, uint32_t addr) {
    asm volatile("ldmatrix.sync.aligned.m8n8.x4.trans.shared.b16 {%0,%1,%2,%3}, [%4];"
        : "=r"(r[0]), "=r"(r[1]), "=r"(r[2]), "=r"(r[3]) : "r"(addr));
}
__device__ __forceinline__ void mma16816(float* d, const uint32_t* a, const uint32_t* b) {
    asm volatile("mma.sync.aligned.m16n8k16.row.col.f32.bf16.bf16.f32 "
        "{%0,%1,%2,%3}, {%4,%5,%6,%7}, {%8,%9}, {%0,%1,%2,%3};"
        : "+f"(d[0]), "+f"(d[1]), "+f"(d[2]), "+f"(d[3])
        : "r"(a[0]), "r"(a[1]), "r"(a[2]), "r"(a[3]), "r"(b[0]), "r"(b[1]));
}
__device__ __forceinline__ uint32_t swz(uint32_t off) { return off ^ ((off >> 3) & 0x70); }

__device__ __forceinline__ void pack_hl(float a, float b, uint32_t& hi, uint32_t& lo) {
    __nv_bfloat162 hh = __floats2bfloat162_rn(a, b);
    float ra = a - __bfloat162float(hh.x);
    float rb = b - __bfloat162float(hh.y);
    __nv_bfloat162 ll = __floats2bfloat162_rn(ra, rb);
    hi = *reinterpret_cast<uint32_t*>(&hh);
    lo = *reinterpret_cast<uint32_t*>(&ll);
}

// ---------------- split conversion kernels ----------------
__global__ void split_k(const float* __restrict__ in, int n)
{
    int base = (blockIdx.x * blockDim.x + threadIdx.x) * 4;
    if (base >= n) return;
    float4 v = *(const float4*)(in + base);
    float vv[4] = {v.x, v.y, v.z, v.w};
    __nv_bfloat16 h[4], l[4];
    #pragma unroll
    for (int j = 0; j < 4; j++) {
        h[j] = __float2bfloat16(vv[j]);
        l[j] = __float2bfloat16(vv[j] - __bfloat162float(h[j]));
    }
    *(__nv_bfloat162*)(g_xh + base)     = __nv_bfloat162{h[0], h[1]};
    *(__nv_bfloat162*)(g_xh + base + 2) = __nv_bfloat162{h[2], h[3]};
    *(__nv_bfloat162*)(g_xl + base)     = __nv_bfloat162{l[0], l[1]};
    *(__nv_bfloat162*)(g_xl + base + 2) = __nv_bfloat162{l[2], l[3]};
}

template<int W>
__global__ void tsplit_k(const float* __restrict__ w)
{
    const int K = 1024;
    const int N = (W == 1) ? 3072 : 1024;
    __nv_bfloat16* th = (W == 1) ? g_w1h : g_w2h;
    __nv_bfloat16* tl = (W == 1) ? g_w1l : g_w2l;
    __shared__ float t[32][33];
    int n0 = blockIdx.x * 32, k0 = blockIdx.y * 32;
    int tx = threadIdx.x, ty = threadIdx.y;
    #pragma unroll
    for (int i = 0; i < 32; i += 8)
        t[ty + i][tx] = w[(size_t)(k0 + ty + i) * N + n0 + tx];
    __syncthreads();
    #pragma unroll
    for (int i = 0; i < 32; i += 8) {
        float v = t[tx][ty + i];
        __nv_bfloat16 h = __float2bfloat16(v);
        __nv_bfloat16 l = __float2bfloat16(v - __bfloat162float(h));
        th[(size_t)(n0 + ty + i) * K + k0 + tx] = h;
        tl[(size_t)(n0 + ty + i) * K + k0 + tx] = l;
    }
}

// ---------------- HMMA bf16x3 GEMM, 256x128 tile, 512 threads ----------------
// Stage layout: Ah[0,32K) Al[32K,64K) Bh[64K,80K) Bl[80K,96K); 2 stages = 192KB.
static constexpr int ST2_BYTES   = 98304;
static constexpr int SMEM_TOTAL2 = 2 * ST2_BYTES;   // 196608

__device__ __forceinline__ void load_stage2(uint32_t sbase,
                                            const __nv_bfloat16* Ah, const __nv_bfloat16* Al,
                                            const __nv_bfloat16* Bh, const __nv_bfloat16* Bl,
                                            int mBase, int nBase, int K, int k0, int tid)
{
    const char* gah = (const char*)(Ah + (size_t)mBase * K + k0);
    const char* gal = (const char*)(Al + (size_t)mBase * K + k0);
    #pragma unroll
    for (int i = 0; i < 4; i++) {
        int id = tid + i * 512;          // 0..2047 -> 256 rows x 8 cp
        int r  = id >> 3;
        int cb = (id & 7) * 16;
        uint32_t off = swz((uint32_t)(r * 128 + cb));
        cp_async16(sbase + off,         gah + (size_t)r * K * 2 + cb);
        cp_async16(sbase + 32768 + off, gal + (size_t)r * K * 2 + cb);
    }
    const char* gbh = (const char*)(Bh + (size_t)nBase * K + k0);
    const char* gbl = (const char*)(Bl + (size_t)nBase * K + k0);
    #pragma unroll
    for (int i = 0; i < 2; i++) {
        int id = tid + i * 512;          // 0..1023 -> 128 rows x 8 cp
        int r  = id >> 3;
        int cb = (id & 7) * 16;
        uint32_t off = swz((uint32_t)(r * 128 + cb));
        cp_async16(sbase + 65536 + off, gbh + (size_t)r * K * 2 + cb);
        cp_async16(sbase + 81920 + off, gbl + (size_t)r * K * 2 + cb);
    }
}

template<int MODE>   // 1 = QKV scatter (bf16 hi/lo), 0 = proj store fp32
__global__ __launch_bounds__(512, 1) void tgemm(const float* __restrict__ bias,
                                                float* __restrict__ C)
{
    const int K = 1024;
    const int N = (MODE == 1) ? 3072 : 1024;
    const __nv_bfloat16* Ah = (MODE == 1) ? g_xh : g_ah;
    const __nv_bfloat16* Al = (MODE == 1) ? g_xl : g_al;
    const __nv_bfloat16* Bh = (MODE == 1) ? g_w1h : g_w2h;
    const __nv_bfloat16* Bl = (MODE == 1) ? g_w1l : g_w2l;

    extern __shared__ char smem[];
    uint32_t sb = smem_u32(smem);
    int tid = threadIdx.x;
    int wid = tid >> 5, l = tid & 31;
    int M0 = (wid & 7) * 32;      // 8 warps along M (32 rows each)
    int N0 = (wid >> 3) * 64;     // 2 warps along N (64 cols each)
    int mBase = blockIdx.y * 256, nBase = blockIdx.x * 128;

    float acc[2][8][4];
    #pragma unroll
    for (int mi = 0; mi < 2; mi++)
        #pragma unroll
        for (int nj = 0; nj < 8; nj++)
            #pragma unroll
            for (int k = 0; k < 4; k++) acc[mi][nj][k] = 0.f;

    int aRow = (l & 7) + ((l >> 3) & 1) * 8;
    int aCb  = ((l >> 4) & 1) * 16;
    int bRow = (l & 7) + ((l >> 4) & 1) * 8;
    int bCb  = ((l >> 3) & 1) * 16;

    const int NK = K / 64;
    load_stage2(sb,             Ah, Al, Bh, Bl, mBase, nBase, K, 0,  tid); cp_commit();
    load_stage2(sb + ST2_BYTES, Ah, Al, Bh, Bl, mBase, nBase, K, 64, tid); cp_commit();

    for (int ko = 0; ko < NK; ko++) {
        cp_wait1();
        __syncthreads();
        uint32_t stage = sb + (ko & 1) * ST2_BYTES;

        #pragma unroll
        for (int ks = 0; ks < 4; ks++) {
            // cache A hi/lo fragments for this ks (reused across passes)
            uint32_t rah[2][4], ral[2][4];
            #pragma unroll
            for (int mi = 0; mi < 2; mi++) {
                uint32_t aoff = swz((uint32_t)((M0 + mi*16 + aRow) * 128 + ks*32 + aCb));
                ldm_x4(rah[mi], stage + aoff);
                ldm_x4(ral[mi], stage + 32768 + aoff);
            }
            #pragma unroll
            for (int p = 0; p < 3; p++) {
                uint32_t bT = stage + 65536 + (p == 1 ? 16384 : 0);   // Bh,Bl,Bh
                uint32_t (*ra)[4] = (p == 2) ? ral : rah;             // Ah,Ah,Al
                uint32_t rb4[4][4];
                #pragma unroll
                for (int nq = 0; nq < 4; nq++)
                    ldm_x4(rb4[nq], bT + swz((uint32_t)((N0 + nq*16 + bRow) * 128 + ks*32 + bCb)));
                #pragma unroll
                for (int mi = 0; mi < 2; mi++)
                    #pragma unroll
                    for (int nj = 0; nj < 8; nj++)
                        mma16816(acc[mi][nj], ra[mi], &rb4[nj >> 1][(nj & 1) * 2]);
            }
        }
        __syncthreads();
        if (ko + 2 < NK)
            load_stage2(sb + (ko & 1) * ST2_BYTES, Ah, Al, Bh, Bl, mBase, nBase, K, (ko + 2) * 64, tid);
        cp_commit();
    }

    #pragma unroll
    for (int mi = 0; mi < 2; mi++) {
        #pragma unroll
        for (int half = 0; half < 2; half++) {
            int m = mBase + M0 + mi * 16 + (l >> 2) + half * 8;
            #pragma unroll
            for (int nj = 0; nj < 8; nj++) {
                int n = nBase + N0 + nj * 8 + (l & 3) * 2;
                float v0 = acc[mi][nj][half * 2 + 0] + bias[n];
                float v1 = acc[mi][nj][half * 2 + 1] + bias[n + 1];
                if (MODE == 1) {
                    int which = n >> 10;
                    int dc = n & 1023;
                    int h = dc >> 6, dh = dc & 63;
                    int b = m >> 10, s2 = m & 1023;
                    size_t gi = (((size_t)(b * Hh + h)) * Sq + s2) * DHd + dh;
                    if (which == 0) { v0 *= 0.125f; v1 *= 0.125f; }
                    uint32_t hh, ll;
                    pack_hl(v0, v1, hh, ll);
                    if (which == 0)      { *(uint32_t*)&g_Qh[gi] = hh; *(uint32_t*)&g_Ql[gi] = ll; }
                    else if (which == 1) { *(uint32_t*)&g_Kh[gi] = hh; *(uint32_t*)&g_Kl[gi] = ll; }
                    else                 { *(uint32_t*)&g_Vh[gi] = hh; *(uint32_t*)&g_Vl[gi] = ll; }
                } else {
                    C[(size_t)m * N + n]     = v0;
                    C[(size_t)m * N + n + 1] = v1;
                }
            }
        }
    }
}

// ---------------- tensor-core causal flash attention (unchanged) ----------------
static constexpr int FL_SMEM = 32768 + 2 * 32768;

__device__ __forceinline__ void load_kv(uint32_t sdst, int bh, int kt, int tid)
{
    const __nv_bfloat16* srcs[4] = {g_Kh, g_Kl, g_Vh, g_Vl};
    size_t base = (size_t)bh * Sq * DHd + (size_t)kt * 64 * DHd;
    #pragma unroll
    for (int t = 0; t < 4; t++) {
        const char* g = (const char*)(srcs[t] + base);
        uint32_t sd = sdst + t * 8192;
        #pragma unroll
        for (int i = 0; i < 2; i++) {
            int id = tid + i * 256;
            int r  = id >> 3;
            int cb = (id & 7) * 16;
            cp_async16(sd + swz((uint32_t)(r * 128 + cb)), g + (size_t)r * 128 + cb);
        }
    }
}

__global__ __launch_bounds__(256) void flash_mma()
{
    extern __shared__ char smem[];
    uint32_t sb = smem_u32(smem);
    int tid = threadIdx.x;
    int w = tid >> 5, l = tid & 31;

    int qc = 7 - (blockIdx.x >> 6);
    int bh = blockIdx.x & 63;
    int qBase = qc * 128;

    {
        const char* gh = (const char*)(g_Qh + (size_t)bh * Sq * DHd + (size_t)qBase * DHd);
        const char* gl = (const char*)(g_Ql + (size_t)bh * Sq * DHd + (size_t)qBase * DHd);
        #pragma unroll
        for (int i = 0; i < 4; i++) {
            int id = tid + i * 256;
            int r  = id >> 3;
            int cb = (id & 7) * 16;
            cp_async16(sb +         swz((uint32_t)(r * 128 + cb)), gh + (size_t)r * 128 + cb);
            cp_async16(sb + 16384 + swz((uint32_t)(r * 128 + cb)), gl + (size_t)r * 128 + cb);
        }
    }
    load_kv(sb + 32768, bh, 0, tid);
    cp_commit();
    int nT = (qc + 1) * 2;
    load_kv(sb + 32768 + 32768, bh, 1, tid);
    cp_commit();

    cp_wait1();
    __syncthreads();

    int aRow = (l & 7) + ((l >> 3) & 1) * 8;
    int aCb  = ((l >> 4) & 1) * 16;
    int bRow = (l & 7) + ((l >> 4) & 1) * 8;
    int bCb  = ((l >> 3) & 1) * 16;
    int vRow = (l & 7) + ((l >> 3) & 1) * 8;
    int vCb  = ((l >> 4) & 1) * 16;

    uint32_t qh[4][4], ql[4][4];
    #pragma unroll
    for (int ks = 0; ks < 4; ks++) {
        ldm_x4(qh[ks], sb +         swz((uint32_t)((w*16 + aRow) * 128 + ks*32 + aCb)));
        ldm_x4(ql[ks], sb + 16384 + swz((uint32_t)((w*16 + aRow) * 128 + ks*32 + aCb)));
    }

    float o[8][4];
    #pragma unroll
    for (int nj = 0; nj < 8; nj++)
        #pragma unroll
        for (int k = 0; k < 4; k++) o[nj][k] = 0.f;
    float m0 = -1e30f, m1 = -1e30f, l0 = 0.f, l1 = 0.f;

    for (int kt = 0; kt < nT; kt++) {
        cp_wait1();
        __syncthreads();
        uint32_t stage = sb + 32768 + (kt & 1) * 32768;

        bool skip = (kt * 64 > qBase + w * 16 + 15);
        if (!skip) {
            float sacc[8][4];
            #pragma unroll
            for (int nj = 0; nj < 8; nj++)
                #pragma unroll
                for (int k = 0; k < 4; k++) sacc[nj][k] = 0.f;

            #pragma unroll
            for (int ks = 0; ks < 4; ks++) {
                #pragma unroll
                for (int nq = 0; nq < 4; nq++) {
                    uint32_t kh4[4], kl4[4];
                    ldm_x4(kh4, stage +        swz((uint32_t)((nq*16 + bRow) * 128 + ks*32 + bCb)));
                    ldm_x4(kl4, stage + 8192 + swz((uint32_t)((nq*16 + bRow) * 128 + ks*32 + bCb)));
                    mma16816(sacc[2*nq],   qh[ks], &kh4[0]);
                    mma16816(sacc[2*nq+1], qh[ks], &kh4[2]);
                    mma16816(sacc[2*nq],   qh[ks], &kl4[0]);
                    mma16816(sacc[2*nq+1], qh[ks], &kl4[2]);
                    mma16816(sacc[2*nq],   ql[ks], &kh4[0]);
                    mma16816(sacc[2*nq+1], ql[ks], &kh4[2]);
                }
            }

            int r0 = qBase + w * 16 + (l >> 2);
            if (kt * 64 + 63 > r0) {
                int kc = kt * 64 + (l & 3) * 2;
                #pragma unroll
                for (int nj = 0; nj < 8; nj++) {
                    int k0 = kc + nj * 8;
                    if (k0     > r0)     sacc[nj][0] = -1e30f;
                    if (k0 + 1 > r0)     sacc[nj][1] = -1e30f;
                    if (k0     > r0 + 8) sacc[nj][2] = -1e30f;
                    if (k0 + 1 > r0 + 8) sacc[nj][3] = -1e30f;
                }
            }

            float mx0 = -1e30f, mx1 = -1e30f;
            #pragma unroll
            for (int nj = 0; nj < 8; nj++) {
                mx0 = fmaxf(mx0, fmaxf(sacc[nj][0], sacc[nj][1]));
                mx1 = fmaxf(mx1, fmaxf(sacc[nj][2], sacc[nj][3]));
            }
            mx0 = fmaxf(mx0, __shfl_xor_sync(0xffffffffu, mx0, 1));
            mx0 = fmaxf(mx0, __shfl_xor_sync(0xffffffffu, mx0, 2));
            mx1 = fmaxf(mx1, __shfl_xor_sync(0xffffffffu, mx1, 1));
            mx1 = fmaxf(mx1, __shfl_xor_sync(0xffffffffu, mx1, 2));
            float mn0 = fmaxf(m0, mx0), mn1 = fmaxf(m1, mx1);
            float sc0 = __expf(m0 - mn0), sc1 = __expf(m1 - mn1);
            l0 *= sc0; l1 *= sc1;
            #pragma unroll
            for (int nj = 0; nj < 8; nj++) {
                o[nj][0] *= sc0; o[nj][1] *= sc0;
                o[nj][2] *= sc1; o[nj][3] *= sc1;
            }
            #pragma unroll
            for (int nj = 0; nj < 8; nj++) {
                sacc[nj][0] = __expf(sacc[nj][0] - mn0); l0 += sacc[nj][0];
                sacc[nj][1] = __expf(sacc[nj][1] - mn0); l0 += sacc[nj][1];
                sacc[nj][2] = __expf(sacc[nj][2] - mn1); l1 += sacc[nj][2];
                sacc[nj][3] = __expf(sacc[nj][3] - mn1); l1 += sacc[nj][3];
            }
            m0 = mn0; m1 = mn1;

            uint32_t pah[4][4], pal[4][4];
            #pragma unroll
            for (int ks = 0; ks < 4; ks++) {
                pack_hl(sacc[2*ks][0],   sacc[2*ks][1],   pah[ks][0], pal[ks][0]);
                pack_hl(sacc[2*ks][2],   sacc[2*ks][3],   pah[ks][1], pal[ks][1]);
                pack_hl(sacc[2*ks+1][0], sacc[2*ks+1][1], pah[ks][2], pal[ks][2]);
                pack_hl(sacc[2*ks+1][2], sacc[2*ks+1][3], pah[ks][3], pal[ks][3]);
            }

            uint32_t vStage = stage + 16384;
            #pragma unroll
            for (int ks = 0; ks < 4; ks++) {
                #pragma unroll
                for (int nq = 0; nq < 4; nq++) {
                    uint32_t vh4[4], vl4[4];
                    ldm_x4_t(vh4, vStage +        swz((uint32_t)((ks*16 + vRow) * 128 + nq*32 + vCb)));
                    ldm_x4_t(vl4, vStage + 8192 + swz((uint32_t)((ks*16 + vRow) * 128 + nq*32 + vCb)));
                    mma16816(o[2*nq],   pah[ks], &vh4[0]);
                    mma16816(o[2*nq+1], pah[ks], &vh4[2]);
                    mma16816(o[2*nq],   pah[ks], &vl4[0]);
                    mma16816(o[2*nq+1], pah[ks], &vl4[2]);
                    mma16816(o[2*nq],   pal[ks], &vh4[0]);
                    mma16816(o[2*nq+1], pal[ks], &vh4[2]);
                }
            }
        }

        __syncthreads();
        if (kt + 2 < nT) load_kv(sb + 32768 + (kt & 1) * 32768, bh, kt + 2, tid);
        cp_commit();
    }
    cp_wait0();

    l0 += __shfl_xor_sync(0xffffffffu, l0, 1);
    l0 += __shfl_xor_sync(0xffffffffu, l0, 2);
    l1 += __shfl_xor_sync(0xffffffffu, l1, 1);
    l1 += __shfl_xor_sync(0xffffffffu, l1, 2);
    float inv0 = 1.f / l0, inv1 = 1.f / l1;

    int b = bh >> 4, h = bh & 15;
    int row0 = qBase + w * 16 + (l >> 2);
    #pragma unroll
    for (int half = 0; half < 2; half++) {
        int row = row0 + half * 8;
        float inv = half ? inv1 : inv0;
        #pragma unroll
        for (int nj = 0; nj < 8; nj++) {
            int col = h * 64 + nj * 8 + (l & 3) * 2;
            float v0 = o[nj][half * 2 + 0] * inv;
            float v1 = o[nj][half * 2 + 1] * inv;
            uint32_t hh, ll;
            pack_hl(v0, v1, hh, ll);
            size_t gi = (size_t)(b * Sq + row) * Dm + col;
            *(uint32_t*)&g_ah[gi] = hh;
            *(uint32_t*)&g_al[gi] = ll;
        }
    }
}

// ---------------------------------------------------------------------------
extern "C" void kernel_launch(void* const* d_in, const int* in_sizes, int n_in,
                              void* d_out, int out_size)
{
    (void)in_sizes; (void)n_in; (void)out_size;
    const float* x  = (const float*)d_in[0];
    const float* w1 = (const float*)d_in[1];
    const float* b1 = (const float*)d_in[2];
    const float* w2 = (const float*)d_in[3];
    const float* b2 = (const float*)d_in[4];
    float* out = (float*)d_out;

    cudaFuncSetAttribute(tgemm<1>, cudaFuncAttributeMaxDynamicSharedMemorySize, SMEM_TOTAL2);
    cudaFuncSetAttribute(tgemm<0>, cudaFuncAttributeMaxDynamicSharedMemorySize, SMEM_TOTAL2);
    cudaFuncSetAttribute(flash_mma, cudaFuncAttributeMaxDynamicSharedMemorySize, FL_SMEM);

    split_k<<<4096, 256>>>(x, 4096 * 1024);
    tsplit_k<1><<<dim3(3072 / 32, 1024 / 32), dim3(32, 8)>>>(w1);
    tsplit_k<2><<<dim3(1024 / 32, 1024 / 32), dim3(32, 8)>>>(w2);

    tgemm<1><<<dim3(3072 / 128, 4096 / 256), 512, SMEM_TOTAL2>>>(b1, nullptr);
    flash_mma<<<512, 256, FL_SMEM>>>();
    tgemm<0><<<dim3(1024 / 128, 4096 / 256), 512, SMEM_TOTAL2>>>(b2, out);
}

// round 7
// speedup vs baseline: 3.5977x; 1.0049x over previous
#include <cuda_runtime.h>
#include <cuda_bf16.h>
#include <cstdint>
#include <math.h>

#define Bc 4
#define Sq 1024
#define Dm 1024
#define Hh 16
#define DHd 64

// ---------------- device scratch (allocation-free rule) ----------------
static constexpr size_t NNqkv = (size_t)Bc * Hh * Sq * DHd;
__device__ __nv_bfloat16 g_Qh[NNqkv], g_Ql[NNqkv];   // Q pre-scaled by 1/8
__device__ __nv_bfloat16 g_Kh[NNqkv], g_Kl[NNqkv];
__device__ __nv_bfloat16 g_Vh[NNqkv], g_Vl[NNqkv];

__device__ __nv_bfloat16 g_xh[4096*1024], g_xl[4096*1024];
__device__ __nv_bfloat16 g_w1h[3072*1024], g_w1l[3072*1024];
__device__ __nv_bfloat16 g_w2h[1024*1024], g_w2l[1024*1024];
__device__ __nv_bfloat16 g_ah[4096*1024], g_al[4096*1024];

// ---------------- helpers ----------------
__device__ __forceinline__ uint32_t smem_u32(const void* p) {
    uint32_t a;
    asm("{ .reg .u64 t; cvta.to.shared.u64 t, %1; cvt.u32.u64 %0, t; }" : "=r"(a) : "l"(p));
    return a;
}
__device__ __forceinline__ void cp_async16(uint32_t saddr, const void* gaddr) {
    asm volatile("cp.async.cg.shared.global [%0], [%1], 16;" :: "r"(saddr), "l"(gaddr));
}
__device__ __forceinline__ void cp_commit() { asm volatile("cp.async.commit_group;" ::: "memory"); }
__device__ __forceinline__ void cp_wait1()  { asm volatile("cp.async.wait_group 1;"  ::: "memory"); }
__device__ __forceinline__ void cp_wait0()  { asm volatile("cp.async.wait_group 0;"  ::: "memory"); }

__device__ __forceinline__ void ldm_x4(uint32_t* r, uint32_t addr) {
    asm volatile("ldmatrix.sync.aligned.m8n8.x4.shared.b16 {%0,%1,%2,%3}, [%4];"
        : "=r"(r[0]), "=r"(r[1]), "=r"(r[2]), "=r"(r[3]) : "r"(addr));
}
__device__ __forceinline__ void ldm_x4_t(uint32_t* r, uint32_t addr) {
    asm volatile("ldmatrix.sync.aligned.m8n8.x4.trans.shared.b16 {%0,%1,%2,%3}, [%4];"
        : "=r"(r[0]), "=r"(r[1]), "=r"(r[2]), "=r"(r[3]) : "r"(addr));
}
__device__ __forceinline__ void mma16816(float* d, const uint32_t* a, const uint32_t* b) {
    asm volatile("mma.sync.aligned.m16n8k16.row.col.f32.bf16.bf16.f32 "
        "{%0,%1,%2,%3}, {%4,%5,%6,%7}, {%8,%9}, {%0,%1,%2,%3};"
        : "+f"(d[0]), "+f"(d[1]), "+f"(d[2]), "+f"(d[3])
        : "r"(a[0]), "r"(a[1]), "r"(a[2]), "r"(a[3]), "r"(b[0]), "r"(b[1]));
}
__device__ __forceinline__ uint32_t swz(uint32_t off) { return off ^ ((off >> 3) & 0x70); }

__device__ __forceinline__ void pack_hl(float a, float b, uint32_t& hi, uint32_t& lo) {
    __nv_bfloat162 hh = __floats2bfloat162_rn(a, b);
    float ra = a - __bfloat162float(hh.x);
    float rb = b - __bfloat162float(hh.y);
    __nv_bfloat162 ll = __floats2bfloat162_rn(ra, rb);
    hi = *reinterpret_cast<uint32_t*>(&hh);
    lo = *reinterpret_cast<uint32_t*>(&ll);
}

// ---------------- split conversion kernels ----------------
__global__ void split_k(const float* __restrict__ in, int n)
{
    int base = (blockIdx.x * blockDim.x + threadIdx.x) * 4;
    if (base >= n) return;
    float4 v = *(const float4*)(in + base);
    float vv[4] = {v.x, v.y, v.z, v.w};
    __nv_bfloat16 h[4], l[4];
    #pragma unroll
    for (int j = 0; j < 4; j++) {
        h[j] = __float2bfloat16(vv[j]);
        l[j] = __float2bfloat16(vv[j] - __bfloat162float(h[j]));
    }
    *(__nv_bfloat162*)(g_xh + base)     = __nv_bfloat162{h[0], h[1]};
    *(__nv_bfloat162*)(g_xh + base + 2) = __nv_bfloat162{h[2], h[3]};
    *(__nv_bfloat162*)(g_xl + base)     = __nv_bfloat162{l[0], l[1]};
    *(__nv_bfloat162*)(g_xl + base + 2) = __nv_bfloat162{l[2], l[3]};
}

template<int W>
__global__ void tsplit_k(const float* __restrict__ w)
{
    const int K = 1024;
    const int N = (W == 1) ? 3072 : 1024;
    __nv_bfloat16* th = (W == 1) ? g_w1h : g_w2h;
    __nv_bfloat16* tl = (W == 1) ? g_w1l : g_w2l;
    __shared__ float t[32][33];
    int n0 = blockIdx.x * 32, k0 = blockIdx.y * 32;
    int tx = threadIdx.x, ty = threadIdx.y;
    #pragma unroll
    for (int i = 0; i < 32; i += 8)
        t[ty + i][tx] = w[(size_t)(k0 + ty + i) * N + n0 + tx];
    __syncthreads();
    #pragma unroll
    for (int i = 0; i < 32; i += 8) {
        float v = t[tx][ty + i];
        __nv_bfloat16 h = __float2bfloat16(v);
        __nv_bfloat16 l = __float2bfloat16(v - __bfloat162float(h));
        th[(size_t)(n0 + ty + i) * K + k0 + tx] = h;
        tl[(size_t)(n0 + ty + i) * K + k0 + tx] = l;
    }
}

// ---------------- HMMA bf16x3 GEMM, 256x128 tile, 256 threads, warp 64x64 ----
// Stage: Ah[0,32K) Al[32K,64K) Bh[64K,80K) Bl[80K,96K); 2 stages = 192KB.
static constexpr int ST2_BYTES   = 98304;
static constexpr int SMEM_TOTAL2 = 2 * ST2_BYTES;

__device__ __forceinline__ void load_stage2(uint32_t sbase,
                                            const __nv_bfloat16* Ah, const __nv_bfloat16* Al,
                                            const __nv_bfloat16* Bh, const __nv_bfloat16* Bl,
                                            int mBase, int nBase, int K, int k0, int tid)
{
    const char* gah = (const char*)(Ah + (size_t)mBase * K + k0);
    const char* gal = (const char*)(Al + (size_t)mBase * K + k0);
    #pragma unroll
    for (int i = 0; i < 8; i++) {
        int id = tid + i * 256;          // 0..2047 -> 256 rows x 8 cp
        int r  = id >> 3;
        int cb = (id & 7) * 16;
        uint32_t off = swz((uint32_t)(r * 128 + cb));
        cp_async16(sbase + off,         gah + (size_t)r * K * 2 + cb);
        cp_async16(sbase + 32768 + off, gal + (size_t)r * K * 2 + cb);
    }
    const char* gbh = (const char*)(Bh + (size_t)nBase * K + k0);
    const char* gbl = (const char*)(Bl + (size_t)nBase * K + k0);
    #pragma unroll
    for (int i = 0; i < 4; i++) {
        int id = tid + i * 256;          // 0..1023 -> 128 rows x 8 cp
        int r  = id >> 3;
        int cb = (id & 7) * 16;
        uint32_t off = swz((uint32_t)(r * 128 + cb));
        cp_async16(sbase + 65536 + off, gbh + (size_t)r * K * 2 + cb);
        cp_async16(sbase + 81920 + off, gbl + (size_t)r * K * 2 + cb);
    }
}

template<int MODE>   // 1 = QKV scatter (bf16 hi/lo), 0 = proj store fp32
__global__ __launch_bounds__(256, 1) void tgemm(const float* __restrict__ bias,
                                                float* __restrict__ C)
{
    const int K = 1024;
    const int N = (MODE == 1) ? 3072 : 1024;
    const __nv_bfloat16* Ah = (MODE == 1) ? g_xh : g_ah;
    const __nv_bfloat16* Al = (MODE == 1) ? g_xl : g_al;
    const __nv_bfloat16* Bh = (MODE == 1) ? g_w1h : g_w2h;
    const __nv_bfloat16* Bl = (MODE == 1) ? g_w1l : g_w2l;

    extern __shared__ char smem[];
    uint32_t sb = smem_u32(smem);
    int tid = threadIdx.x;
    int wid = tid >> 5, l = tid & 31;
    int M0 = (wid & 3) * 64;      // 4 warps along M, 64 rows each
    int N0 = (wid >> 2) * 64;     // 2 warps along N, 64 cols each
    int mBase = blockIdx.y * 256, nBase = blockIdx.x * 128;

    float acc[4][8][4];
    #pragma unroll
    for (int mi = 0; mi < 4; mi++)
        #pragma unroll
        for (int nj = 0; nj < 8; nj++)
            #pragma unroll
            for (int k = 0; k < 4; k++) acc[mi][nj][k] = 0.f;

    int aRow = (l & 7) + ((l >> 3) & 1) * 8;
    int aCb  = ((l >> 4) & 1) * 16;
    int bRow = (l & 7) + ((l >> 4) & 1) * 8;
    int bCb  = ((l >> 3) & 1) * 16;

    const int NK = K / 64;
    load_stage2(sb,             Ah, Al, Bh, Bl, mBase, nBase, K, 0,  tid); cp_commit();
    load_stage2(sb + ST2_BYTES, Ah, Al, Bh, Bl, mBase, nBase, K, 64, tid); cp_commit();

    for (int ko = 0; ko < NK; ko++) {
        cp_wait1();
        __syncthreads();
        uint32_t stage = sb + (ko & 1) * ST2_BYTES;

        #pragma unroll
        for (int ks = 0; ks < 4; ks++) {
            // load ALL fragments for this ks once; 3 passes run from registers
            uint32_t rah[4][4], ral[4][4], rbh[4][4], rbl[4][4];
            #pragma unroll
            for (int mi = 0; mi < 4; mi++) {
                uint32_t aoff = swz((uint32_t)((M0 + mi*16 + aRow) * 128 + ks*32 + aCb));
                ldm_x4(rah[mi], stage + aoff);
                ldm_x4(ral[mi], stage + 32768 + aoff);
            }
            #pragma unroll
            for (int nq = 0; nq < 4; nq++) {
                uint32_t boff = swz((uint32_t)((N0 + nq*16 + bRow) * 128 + ks*32 + bCb));
                ldm_x4(rbh[nq], stage + 65536 + boff);
                ldm_x4(rbl[nq], stage + 81920 + boff);
            }
            #pragma unroll
            for (int mi = 0; mi < 4; mi++)
                #pragma unroll
                for (int nj = 0; nj < 8; nj++) {
                    const uint32_t* bh = &rbh[nj >> 1][(nj & 1) * 2];
                    const uint32_t* bl = &rbl[nj >> 1][(nj & 1) * 2];
                    mma16816(acc[mi][nj], rah[mi], bh);
                    mma16816(acc[mi][nj], rah[mi], bl);
                    mma16816(acc[mi][nj], ral[mi], bh);
                }
        }
        __syncthreads();
        if (ko + 2 < NK)
            load_stage2(sb + (ko & 1) * ST2_BYTES, Ah, Al, Bh, Bl, mBase, nBase, K, (ko + 2) * 64, tid);
        cp_commit();
    }

    #pragma unroll
    for (int mi = 0; mi < 4; mi++) {
        #pragma unroll
        for (int half = 0; half < 2; half++) {
            int m = mBase + M0 + mi * 16 + (l >> 2) + half * 8;
            #pragma unroll
            for (int nj = 0; nj < 8; nj++) {
                int n = nBase + N0 + nj * 8 + (l & 3) * 2;
                float v0 = acc[mi][nj][half * 2 + 0] + bias[n];
                float v1 = acc[mi][nj][half * 2 + 1] + bias[n + 1];
                if (MODE == 1) {
                    int which = n >> 10;
                    int dc = n & 1023;
                    int h = dc >> 6, dh = dc & 63;
                    int b = m >> 10, s2 = m & 1023;
                    size_t gi = (((size_t)(b * Hh + h)) * Sq + s2) * DHd + dh;
                    if (which == 0) { v0 *= 0.125f; v1 *= 0.125f; }
                    uint32_t hh, ll;
                    pack_hl(v0, v1, hh, ll);
                    if (which == 0)      { *(uint32_t*)&g_Qh[gi] = hh; *(uint32_t*)&g_Ql[gi] = ll; }
                    else if (which == 1) { *(uint32_t*)&g_Kh[gi] = hh; *(uint32_t*)&g_Kl[gi] = ll; }
                    else                 { *(uint32_t*)&g_Vh[gi] = hh; *(uint32_t*)&g_Vl[gi] = ll; }
                } else {
                    C[(size_t)m * N + n]     = v0;
                    C[(size_t)m * N + n + 1] = v1;
                }
            }
        }
    }
}

// ---------------- tensor-core causal flash attention (unchanged) ----------------
static constexpr int FL_SMEM = 32768 + 2 * 32768;

__device__ __forceinline__ void load_kv(uint32_t sdst, int bh, int kt, int tid)
{
    const __nv_bfloat16* srcs[4] = {g_Kh, g_Kl, g_Vh, g_Vl};
    size_t base = (size_t)bh * Sq * DHd + (size_t)kt * 64 * DHd;
    #pragma unroll
    for (int t = 0; t < 4; t++) {
        const char* g = (const char*)(srcs[t] + base);
        uint32_t sd = sdst + t * 8192;
        #pragma unroll
        for (int i = 0; i < 2; i++) {
            int id = tid + i * 256;
            int r  = id >> 3;
            int cb = (id & 7) * 16;
            cp_async16(sd + swz((uint32_t)(r * 128 + cb)), g + (size_t)r * 128 + cb);
        }
    }
}

__global__ __launch_bounds__(256) void flash_mma()
{
    extern __shared__ char smem[];
    uint32_t sb = smem_u32(smem);
    int tid = threadIdx.x;
    int w = tid >> 5, l = tid & 31;

    int qc = 7 - (blockIdx.x >> 6);
    int bh = blockIdx.x & 63;
    int qBase = qc * 128;

    {
        const char* gh = (const char*)(g_Qh + (size_t)bh * Sq * DHd + (size_t)qBase * DHd);
        const char* gl = (const char*)(g_Ql + (size_t)bh * Sq * DHd + (size_t)qBase * DHd);
        #pragma unroll
        for (int i = 0; i < 4; i++) {
            int id = tid + i * 256;
            int r  = id >> 3;
            int cb = (id & 7) * 16;
            cp_async16(sb +         swz((uint32_t)(r * 128 + cb)), gh + (size_t)r * 128 + cb);
            cp_async16(sb + 16384 + swz((uint32_t)(r * 128 + cb)), gl + (size_t)r * 128 + cb);
        }
    }
    load_kv(sb + 32768, bh, 0, tid);
    cp_commit();
    int nT = (qc + 1) * 2;
    load_kv(sb + 32768 + 32768, bh, 1, tid);
    cp_commit();

    cp_wait1();
    __syncthreads();

    int aRow = (l & 7) + ((l >> 3) & 1) * 8;
    int aCb  = ((l >> 4) & 1) * 16;
    int bRow = (l & 7) + ((l >> 4) & 1) * 8;
    int bCb  = ((l >> 3) & 1) * 16;
    int vRow = (l & 7) + ((l >> 3) & 1) * 8;
    int vCb  = ((l >> 4) & 1) * 16;

    uint32_t qh[4][4], ql[4][4];
    #pragma unroll
    for (int ks = 0; ks < 4; ks++) {
        ldm_x4(qh[ks], sb +         swz((uint32_t)((w*16 + aRow) * 128 + ks*32 + aCb)));
        ldm_x4(ql[ks], sb + 16384 + swz((uint32_t)((w*16 + aRow) * 128 + ks*32 + aCb)));
    }

    float o[8][4];
    #pragma unroll
    for (int nj = 0; nj < 8; nj++)
        #pragma unroll
        for (int k = 0; k < 4; k++) o[nj][k] = 0.f;
    float m0 = -1e30f, m1 = -1e30f, l0 = 0.f, l1 = 0.f;

    for (int kt = 0; kt < nT; kt++) {
        cp_wait1();
        __syncthreads();
        uint32_t stage = sb + 32768 + (kt & 1) * 32768;

        bool skip = (kt * 64 > qBase + w * 16 + 15);
        if (!skip) {
            float sacc[8][4];
            #pragma unroll
            for (int nj = 0; nj < 8; nj++)
                #pragma unroll
                for (int k = 0; k < 4; k++) sacc[nj][k] = 0.f;

            #pragma unroll
            for (int ks = 0; ks < 4; ks++) {
                #pragma unroll
                for (int nq = 0; nq < 4; nq++) {
                    uint32_t kh4[4], kl4[4];
                    ldm_x4(kh4, stage +        swz((uint32_t)((nq*16 + bRow) * 128 + ks*32 + bCb)));
                    ldm_x4(kl4, stage + 8192 + swz((uint32_t)((nq*16 + bRow) * 128 + ks*32 + bCb)));
                    mma16816(sacc[2*nq],   qh[ks], &kh4[0]);
                    mma16816(sacc[2*nq+1], qh[ks], &kh4[2]);
                    mma16816(sacc[2*nq],   qh[ks], &kl4[0]);
                    mma16816(sacc[2*nq+1], qh[ks], &kl4[2]);
                    mma16816(sacc[2*nq],   ql[ks], &kh4[0]);
                    mma16816(sacc[2*nq+1], ql[ks], &kh4[2]);
                }
            }

            int r0 = qBase + w * 16 + (l >> 2);
            if (kt * 64 + 63 > r0) {
                int kc = kt * 64 + (l & 3) * 2;
                #pragma unroll
                for (int nj = 0; nj < 8; nj++) {
                    int k0 = kc + nj * 8;
                    if (k0     > r0)     sacc[nj][0] = -1e30f;
                    if (k0 + 1 > r0)     sacc[nj][1] = -1e30f;
                    if (k0     > r0 + 8) sacc[nj][2] = -1e30f;
                    if (k0 + 1 > r0 + 8) sacc[nj][3] = -1e30f;
                }
            }

            float mx0 = -1e30f, mx1 = -1e30f;
            #pragma unroll
            for (int nj = 0; nj < 8; nj++) {
                mx0 = fmaxf(mx0, fmaxf(sacc[nj][0], sacc[nj][1]));
                mx1 = fmaxf(mx1, fmaxf(sacc[nj][2], sacc[nj][3]));
            }
            mx0 = fmaxf(mx0, __shfl_xor_sync(0xffffffffu, mx0, 1));
            mx0 = fmaxf(mx0, __shfl_xor_sync(0xffffffffu, mx0, 2));
            mx1 = fmaxf(mx1, __shfl_xor_sync(0xffffffffu, mx1, 1));
            mx1 = fmaxf(mx1, __shfl_xor_sync(0xffffffffu, mx1, 2));
            float mn0 = fmaxf(m0, mx0), mn1 = fmaxf(m1, mx1);
            float sc0 = __expf(m0 - mn0), sc1 = __expf(m1 - mn1);
            l0 *= sc0; l1 *= sc1;
            #pragma unroll
            for (int nj = 0; nj < 8; nj++) {
                o[nj][0] *= sc0; o[nj][1] *= sc0;
                o[nj][2] *= sc1; o[nj][3] *= sc1;
            }
            #pragma unroll
            for (int nj = 0; nj < 8; nj++) {
                sacc[nj][0] = __expf(sacc[nj][0] - mn0); l0 += sacc[nj][0];
                sacc[nj][1] = __expf(sacc[nj][1] - mn0); l0 += sacc[nj][1];
                sacc[nj][2] = __expf(sacc[nj][2] - mn1); l1 += sacc[nj][2];
                sacc[nj][3] = __expf(sacc[nj][3] - mn1); l1 += sacc[nj][3];
            }
            m0 = mn0; m1 = mn1;

            uint32_t pah[4][4], pal[4][4];
            #pragma unroll
            for (int ks = 0; ks < 4; ks++) {
                pack_hl(sacc[2*ks][0],   sacc[2*ks][1],   pah[ks][0], pal[ks][0]);
                pack_hl(sacc[2*ks][2],   sacc[2*ks][3],   pah[ks][1], pal[ks][1]);
                pack_hl(sacc[2*ks+1][0], sacc[2*ks+1][1], pah[ks][2], pal[ks][2]);
                pack_hl(sacc[2*ks+1][2], sacc[2*ks+1][3], pah[ks][3], pal[ks][3]);
            }

            uint32_t vStage = stage + 16384;
            #pragma unroll
            for (int ks = 0; ks < 4; ks++) {
                #pragma unroll
                for (int nq = 0; nq < 4; nq++) {
                    uint32_t vh4[4], vl4[4];
                    ldm_x4_t(vh4, vStage +        swz((uint32_t)((ks*16 + vRow) * 128 + nq*32 + vCb)));
                    ldm_x4_t(vl4, vStage + 8192 + swz((uint32_t)((ks*16 + vRow) * 128 + nq*32 + vCb)));
                    mma16816(o[2*nq],   pah[ks], &vh4[0]);
                    mma16816(o[2*nq+1], pah[ks], &vh4[2]);
                    mma16816(o[2*nq],   pah[ks], &vl4[0]);
                    mma16816(o[2*nq+1], pah[ks], &vl4[2]);
                    mma16816(o[2*nq],   pal[ks], &vh4[0]);
                    mma16816(o[2*nq+1], pal[ks], &vh4[2]);
                }
            }
        }

        __syncthreads();
        if (kt + 2 < nT) load_kv(sb + 32768 + (kt & 1) * 32768, bh, kt + 2, tid);
        cp_commit();
    }
    cp_wait0();

    l0 += __shfl_xor_sync(0xffffffffu, l0, 1);
    l0 += __shfl_xor_sync(0xffffffffu, l0, 2);
    l1 += __shfl_xor_sync(0xffffffffu, l1, 1);
    l1 += __shfl_xor_sync(0xffffffffu, l1, 2);
    float inv0 = 1.f / l0, inv1 = 1.f / l1;

    int b = bh >> 4, h = bh & 15;
    int row0 = qBase + w * 16 + (l >> 2);
    #pragma unroll
    for (int half = 0; half < 2; half++) {
        int row = row0 + half * 8;
        float inv = half ? inv1 : inv0;
        #pragma unroll
        for (int nj = 0; nj < 8; nj++) {
            int col = h * 64 + nj * 8 + (l & 3) * 2;
            float v0 = o[nj][half * 2 + 0] * inv;
            float v1 = o[nj][half * 2 + 1] * inv;
            uint32_t hh, ll;
            pack_hl(v0, v1, hh, ll);
            size_t gi = (size_t)(b * Sq + row) * Dm + col;
            *(uint32_t*)&g_ah[gi] = hh;
            *(uint32_t*)&g_al[gi] = ll;
        }
    }
}

// ---------------------------------------------------------------------------
extern "C" void kernel_launch(void* const* d_in, const int* in_sizes, int n_in,
                              void* d_out, int out_size)
{
    (void)in_sizes; (void)n_in; (void)out_size;
    const float* x  = (const float*)d_in[0];
    const float* w1 = (const float*)d_in[1];
    const float* b1 = (const float*)d_in[2];
    const float* w2 = (const float*)d_in[3];
    const float* b2 = (const float*)d_in[4];
    float* out = (float*)d_out;

    cudaFuncSetAttribute(tgemm<1>, cudaFuncAttributeMaxDynamicSharedMemorySize, SMEM_TOTAL2);
    cudaFuncSetAttribute(tgemm<0>, cudaFuncAttributeMaxDynamicSharedMemorySize, SMEM_TOTAL2);
    cudaFuncSetAttribute(flash_mma, cudaFuncAttributeMaxDynamicSharedMemorySize, FL_SMEM);

    split_k<<<4096, 256>>>(x, 4096 * 1024);
    tsplit_k<1><<<dim3(3072 / 32, 1024 / 32), dim3(32, 8)>>>(w1);
    tsplit_k<2><<<dim3(1024 / 32, 1024 / 32), dim3(32, 8)>>>(w2);

    tgemm<1><<<dim3(3072 / 128, 4096 / 256), 256, SMEM_TOTAL2>>>(b1, nullptr);
    flash_mma<<<512, 256, FL_SMEM>>>();
    tgemm<0><<<dim3(1024 / 128, 4096 / 256), 256, SMEM_TOTAL2>>>(b2, out);
}

// round 8
// speedup vs baseline: 4.9827x; 1.3850x over previous
#include <cuda_runtime.h>
#include <cuda_fp16.h>
#include <cstdint>
#include <math.h>

#define Bc 4
#define Sq 1024
#define Dm 1024
#define Hh 16
#define DHd 64

// ---------------- device scratch (allocation-free rule) ----------------
static constexpr size_t NNqkv = (size_t)Bc * Hh * Sq * DHd;
__device__ __half g_Qh[NNqkv], g_Ql[NNqkv];   // Q split hi/lo, pre-scaled by 1/8
__device__ __half g_Kx[NNqkv];                // K single fp16
__device__ __half g_Vx[NNqkv];                // V single fp16

__device__ __half g_xh[4096*1024], g_xl[4096*1024];   // x split [m][k]
__device__ __half g_w1x[3072*1024];                   // w1^T single [n][k]
__device__ __half g_w2x[1024*1024];                   // w2^T single [n][k]
__device__ __half g_ah[4096*1024], g_al[4096*1024];   // attn out split [m][k]

// ---------------- helpers ----------------
__device__ __forceinline__ uint32_t smem_u32(const void* p) {
    uint32_t a;
    asm("{ .reg .u64 t; cvta.to.shared.u64 t, %1; cvt.u32.u64 %0, t; }" : "=r"(a) : "l"(p));
    return a;
}
__device__ __forceinline__ void cp_async16(uint32_t saddr, const void* gaddr) {
    asm volatile("cp.async.cg.shared.global [%0], [%1], 16;" :: "r"(saddr), "l"(gaddr));
}
__device__ __forceinline__ void cp_commit() { asm volatile("cp.async.commit_group;" ::: "memory"); }
__device__ __forceinline__ void cp_wait1()  { asm volatile("cp.async.wait_group 1;"  ::: "memory"); }
__device__ __forceinline__ void cp_wait0()  { asm volatile("cp.async.wait_group 0;"  ::: "memory"); }

__device__ __forceinline__ void ldm_x4(uint32_t* r, uint32_t addr) {
    asm volatile("ldmatrix.sync.aligned.m8n8.x4.shared.b16 {%0,%1,%2,%3}, [%4];"
        : "=r"(r[0]), "=r"(r[1]), "=r"(r[2]), "=r"(r[3]) : "r"(addr));
}
__device__ __forceinline__ void ldm_x4_t(uint32_t* r, uint32_t addr) {
    asm volatile("ldmatrix.sync.aligned.m8n8.x4.trans.shared.b16 {%0,%1,%2,%3}, [%4];"
        : "=r"(r[0]), "=r"(r[1]), "=r"(r[2]), "=r"(r[3]) : "r"(addr));
}
__device__ __forceinline__ void mma16816(float* d, const uint32_t* a, const uint32_t* b) {
    asm volatile("mma.sync.aligned.m16n8k16.row.col.f32.f16.f16.f32 "
        "{%0,%1,%2,%3}, {%4,%5,%6,%7}, {%8,%9}, {%0,%1,%2,%3};"
        : "+f"(d[0]), "+f"(d[1]), "+f"(d[2]), "+f"(d[3])
        : "r"(a[0]), "r"(a[1]), "r"(a[2]), "r"(a[3]), "r"(b[0]), "r"(b[1]));
}
__device__ __forceinline__ uint32_t swz(uint32_t off) { return off ^ ((off >> 3) & 0x70); }

// fp16 hi/lo split of a float pair
__device__ __forceinline__ void pack_hl(float a, float b, uint32_t& hi, uint32_t& lo) {
    __half2 hh = __floats2half2_rn(a, b);
    float ra = a - __half2float(__low2half(hh));
    float rb = b - __half2float(__high2half(hh));
    __half2 ll = __floats2half2_rn(ra, rb);
    hi = *reinterpret_cast<uint32_t*>(&hh);
    lo = *reinterpret_cast<uint32_t*>(&ll);
}
__device__ __forceinline__ uint32_t pack_h2(float a, float b) {
    __half2 hh = __floats2half2_rn(a, b);
    return *reinterpret_cast<uint32_t*>(&hh);
}

// ---------------- split conversion kernels ----------------
__global__ void split_k(const float* __restrict__ in, int n)
{
    int base = (blockIdx.x * blockDim.x + threadIdx.x) * 4;
    if (base >= n) return;
    float4 v = *(const float4*)(in + base);
    uint32_t h0, l0, h1, l1;
    pack_hl(v.x, v.y, h0, l0);
    pack_hl(v.z, v.w, h1, l1);
    *(uint32_t*)(g_xh + base)     = h0;
    *(uint32_t*)(g_xh + base + 2) = h1;
    *(uint32_t*)(g_xl + base)     = l0;
    *(uint32_t*)(g_xl + base + 2) = l1;
}

// transpose w[K][N] -> out[n][k], single fp16
template<int W>
__global__ void tsplit_k(const float* __restrict__ w)
{
    const int K = 1024;
    const int N = (W == 1) ? 3072 : 1024;
    __half* th = (W == 1) ? g_w1x : g_w2x;
    __shared__ float t[32][33];
    int n0 = blockIdx.x * 32, k0 = blockIdx.y * 32;
    int tx = threadIdx.x, ty = threadIdx.y;
    #pragma unroll
    for (int i = 0; i < 32; i += 8)
        t[ty + i][tx] = w[(size_t)(k0 + ty + i) * N + n0 + tx];
    __syncthreads();
    #pragma unroll
    for (int i = 0; i < 32; i += 8)
        th[(size_t)(n0 + ty + i) * K + k0 + tx] = __float2half_rn(t[tx][ty + i]);
}

// ---------------- HMMA fp16x2 GEMM, 256x128 tile, 256 threads, warp 64x64 ----
// Stage: Ah[0,32K) Al[32K,64K) B[64K,80K); 2 stages = 160KB.
static constexpr int ST2_BYTES   = 81920;
static constexpr int SMEM_TOTAL2 = 2 * ST2_BYTES;   // 163840

__device__ __forceinline__ void load_stage2(uint32_t sbase,
                                            const __half* Ah, const __half* Al,
                                            const __half* B,
                                            int mBase, int nBase, int K, int k0, int tid)
{
    const char* gah = (const char*)(Ah + (size_t)mBase * K + k0);
    const char* gal = (const char*)(Al + (size_t)mBase * K + k0);
    #pragma unroll
    for (int i = 0; i < 8; i++) {
        int id = tid + i * 256;          // 0..2047 -> 256 rows x 8 cp
        int r  = id >> 3;
        int cb = (id & 7) * 16;
        uint32_t off = swz((uint32_t)(r * 128 + cb));
        cp_async16(sbase + off,         gah + (size_t)r * K * 2 + cb);
        cp_async16(sbase + 32768 + off, gal + (size_t)r * K * 2 + cb);
    }
    const char* gb = (const char*)(B + (size_t)nBase * K + k0);
    #pragma unroll
    for (int i = 0; i < 4; i++) {
        int id = tid + i * 256;          // 0..1023 -> 128 rows x 8 cp
        int r  = id >> 3;
        int cb = (id & 7) * 16;
        cp_async16(sbase + 65536 + swz((uint32_t)(r * 128 + cb)), gb + (size_t)r * K * 2 + cb);
    }
}

template<int MODE>   // 1 = QKV scatter, 0 = proj store fp32
__global__ __launch_bounds__(256, 1) void tgemm(const float* __restrict__ bias,
                                                float* __restrict__ C)
{
    const int K = 1024;
    const int N = (MODE == 1) ? 3072 : 1024;
    const __half* Ah = (MODE == 1) ? g_xh : g_ah;
    const __half* Al = (MODE == 1) ? g_xl : g_al;
    const __half* B  = (MODE == 1) ? g_w1x : g_w2x;

    extern __shared__ char smem[];
    uint32_t sb = smem_u32(smem);
    int tid = threadIdx.x;
    int wid = tid >> 5, l = tid & 31;
    int M0 = (wid & 3) * 64;      // 4 warps along M
    int N0 = (wid >> 2) * 64;     // 2 warps along N
    int mBase = blockIdx.y * 256, nBase = blockIdx.x * 128;

    float acc[4][8][4];
    #pragma unroll
    for (int mi = 0; mi < 4; mi++)
        #pragma unroll
        for (int nj = 0; nj < 8; nj++)
            #pragma unroll
            for (int k = 0; k < 4; k++) acc[mi][nj][k] = 0.f;

    int aRow = (l & 7) + ((l >> 3) & 1) * 8;
    int aCb  = ((l >> 4) & 1) * 16;
    int bRow = (l & 7) + ((l >> 4) & 1) * 8;
    int bCb  = ((l >> 3) & 1) * 16;

    const int NK = K / 64;
    load_stage2(sb,             Ah, Al, B, mBase, nBase, K, 0,  tid); cp_commit();
    load_stage2(sb + ST2_BYTES, Ah, Al, B, mBase, nBase, K, 64, tid); cp_commit();

    for (int ko = 0; ko < NK; ko++) {
        cp_wait1();
        __syncthreads();
        uint32_t stage = sb + (ko & 1) * ST2_BYTES;

        #pragma unroll
        for (int ks = 0; ks < 4; ks++) {
            uint32_t rah[4][4], ral[4][4], rb[4][4];
            #pragma unroll
            for (int mi = 0; mi < 4; mi++) {
                uint32_t aoff = swz((uint32_t)((M0 + mi*16 + aRow) * 128 + ks*32 + aCb));
                ldm_x4(rah[mi], stage + aoff);
                ldm_x4(ral[mi], stage + 32768 + aoff);
            }
            #pragma unroll
            for (int nq = 0; nq < 4; nq++)
                ldm_x4(rb[nq], stage + 65536 + swz((uint32_t)((N0 + nq*16 + bRow) * 128 + ks*32 + bCb)));
            #pragma unroll
            for (int mi = 0; mi < 4; mi++)
                #pragma unroll
                for (int nj = 0; nj < 8; nj++) {
                    const uint32_t* bp = &rb[nj >> 1][(nj & 1) * 2];
                    mma16816(acc[mi][nj], rah[mi], bp);
                    mma16816(acc[mi][nj], ral[mi], bp);
                }
        }
        __syncthreads();
        if (ko + 2 < NK)
            load_stage2(sb + (ko & 1) * ST2_BYTES, Ah, Al, B, mBase, nBase, K, (ko + 2) * 64, tid);
        cp_commit();
    }

    #pragma unroll
    for (int mi = 0; mi < 4; mi++) {
        #pragma unroll
        for (int half = 0; half < 2; half++) {
            int m = mBase + M0 + mi * 16 + (l >> 2) + half * 8;
            #pragma unroll
            for (int nj = 0; nj < 8; nj++) {
                int n = nBase + N0 + nj * 8 + (l & 3) * 2;
                float v0 = acc[mi][nj][half * 2 + 0] + bias[n];
                float v1 = acc[mi][nj][half * 2 + 1] + bias[n + 1];
                if (MODE == 1) {
                    int which = n >> 10;
                    int dc = n & 1023;
                    int h = dc >> 6, dh = dc & 63;
                    int b = m >> 10, s2 = m & 1023;
                    size_t gi = (((size_t)(b * Hh + h)) * Sq + s2) * DHd + dh;
                    if (which == 0) {
                        uint32_t hh, ll;
                        pack_hl(v0 * 0.125f, v1 * 0.125f, hh, ll);
                        *(uint32_t*)&g_Qh[gi] = hh;
                        *(uint32_t*)&g_Ql[gi] = ll;
                    } else if (which == 1) {
                        *(uint32_t*)&g_Kx[gi] = pack_h2(v0, v1);
                    } else {
                        *(uint32_t*)&g_Vx[gi] = pack_h2(v0, v1);
                    }
                } else {
                    C[(size_t)m * N + n]     = v0;
                    C[(size_t)m * N + n + 1] = v1;
                }
            }
        }
    }
}

// ---------------- tensor-core causal flash attention (fp16x2) ----------------
// SMEM: Qh[0,16K) Ql[16K,32K); stages at 32K: {K 8K, V 8K} x 2 = 32K. Total 64K.
static constexpr int FL_SMEM = 32768 + 2 * 16384;

__device__ __forceinline__ void load_kv(uint32_t sdst, int bh, int kt, int tid)
{
    const __half* srcs[2] = {g_Kx, g_Vx};
    size_t base = (size_t)bh * Sq * DHd + (size_t)kt * 64 * DHd;
    #pragma unroll
    for (int t = 0; t < 2; t++) {
        const char* g = (const char*)(srcs[t] + base);
        uint32_t sd = sdst + t * 8192;
        #pragma unroll
        for (int i = 0; i < 2; i++) {
            int id = tid + i * 256;
            int r  = id >> 3;
            int cb = (id & 7) * 16;
            cp_async16(sd + swz((uint32_t)(r * 128 + cb)), g + (size_t)r * 128 + cb);
        }
    }
}

__global__ __launch_bounds__(256) void flash_mma()
{
    extern __shared__ char smem[];
    uint32_t sb = smem_u32(smem);
    int tid = threadIdx.x;
    int w = tid >> 5, l = tid & 31;

    int qc = 7 - (blockIdx.x >> 6);
    int bh = blockIdx.x & 63;
    int qBase = qc * 128;

    {
        const char* gh = (const char*)(g_Qh + (size_t)bh * Sq * DHd + (size_t)qBase * DHd);
        const char* gl = (const char*)(g_Ql + (size_t)bh * Sq * DHd + (size_t)qBase * DHd);
        #pragma unroll
        for (int i = 0; i < 4; i++) {
            int id = tid + i * 256;
            int r  = id >> 3;
            int cb = (id & 7) * 16;
            cp_async16(sb +         swz((uint32_t)(r * 128 + cb)), gh + (size_t)r * 128 + cb);
            cp_async16(sb + 16384 + swz((uint32_t)(r * 128 + cb)), gl + (size_t)r * 128 + cb);
        }
    }
    load_kv(sb + 32768, bh, 0, tid);
    cp_commit();
    int nT = (qc + 1) * 2;
    load_kv(sb + 32768 + 16384, bh, 1, tid);
    cp_commit();

    cp_wait1();
    __syncthreads();

    int aRow = (l & 7) + ((l >> 3) & 1) * 8;
    int aCb  = ((l >> 4) & 1) * 16;
    int bRow = (l & 7) + ((l >> 4) & 1) * 8;
    int bCb  = ((l >> 3) & 1) * 16;
    int vRow = (l & 7) + ((l >> 3) & 1) * 8;
    int vCb  = ((l >> 4) & 1) * 16;

    uint32_t qh[4][4], ql[4][4];
    #pragma unroll
    for (int ks = 0; ks < 4; ks++) {
        ldm_x4(qh[ks], sb +         swz((uint32_t)((w*16 + aRow) * 128 + ks*32 + aCb)));
        ldm_x4(ql[ks], sb + 16384 + swz((uint32_t)((w*16 + aRow) * 128 + ks*32 + aCb)));
    }

    float o[8][4];
    #pragma unroll
    for (int nj = 0; nj < 8; nj++)
        #pragma unroll
        for (int k = 0; k < 4; k++) o[nj][k] = 0.f;
    float m0 = -1e30f, m1 = -1e30f, l0 = 0.f, l1 = 0.f;

    for (int kt = 0; kt < nT; kt++) {
        cp_wait1();
        __syncthreads();
        uint32_t stage = sb + 32768 + (kt & 1) * 16384;

        bool skip = (kt * 64 > qBase + w * 16 + 15);
        if (!skip) {
            float sacc[8][4];
            #pragma unroll
            for (int nj = 0; nj < 8; nj++)
                #pragma unroll
                for (int k = 0; k < 4; k++) sacc[nj][k] = 0.f;

            #pragma unroll
            for (int ks = 0; ks < 4; ks++) {
                #pragma unroll
                for (int nq = 0; nq < 4; nq++) {
                    uint32_t kh4[4];
                    ldm_x4(kh4, stage + swz((uint32_t)((nq*16 + bRow) * 128 + ks*32 + bCb)));
                    mma16816(sacc[2*nq],   qh[ks], &kh4[0]);
                    mma16816(sacc[2*nq+1], qh[ks], &kh4[2]);
                    mma16816(sacc[2*nq],   ql[ks], &kh4[0]);
                    mma16816(sacc[2*nq+1], ql[ks], &kh4[2]);
                }
            }

            int r0 = qBase + w * 16 + (l >> 2);
            if (kt * 64 + 63 > r0) {
                int kc = kt * 64 + (l & 3) * 2;
                #pragma unroll
                for (int nj = 0; nj < 8; nj++) {
                    int k0 = kc + nj * 8;
                    if (k0     > r0)     sacc[nj][0] = -1e30f;
                    if (k0 + 1 > r0)     sacc[nj][1] = -1e30f;
                    if (k0     > r0 + 8) sacc[nj][2] = -1e30f;
                    if (k0 + 1 > r0 + 8) sacc[nj][3] = -1e30f;
                }
            }

            float mx0 = -1e30f, mx1 = -1e30f;
            #pragma unroll
            for (int nj = 0; nj < 8; nj++) {
                mx0 = fmaxf(mx0, fmaxf(sacc[nj][0], sacc[nj][1]));
                mx1 = fmaxf(mx1, fmaxf(sacc[nj][2], sacc[nj][3]));
            }
            mx0 = fmaxf(mx0, __shfl_xor_sync(0xffffffffu, mx0, 1));
            mx0 = fmaxf(mx0, __shfl_xor_sync(0xffffffffu, mx0, 2));
            mx1 = fmaxf(mx1, __shfl_xor_sync(0xffffffffu, mx1, 1));
            mx1 = fmaxf(mx1, __shfl_xor_sync(0xffffffffu, mx1, 2));
            float mn0 = fmaxf(m0, mx0), mn1 = fmaxf(m1, mx1);
            float sc0 = __expf(m0 - mn0), sc1 = __expf(m1 - mn1);
            l0 *= sc0; l1 *= sc1;
            #pragma unroll
            for (int nj = 0; nj < 8; nj++) {
                o[nj][0] *= sc0; o[nj][1] *= sc0;
                o[nj][2] *= sc1; o[nj][3] *= sc1;
            }
            #pragma unroll
            for (int nj = 0; nj < 8; nj++) {
                sacc[nj][0] = __expf(sacc[nj][0] - mn0); l0 += sacc[nj][0];
                sacc[nj][1] = __expf(sacc[nj][1] - mn0); l0 += sacc[nj][1];
                sacc[nj][2] = __expf(sacc[nj][2] - mn1); l1 += sacc[nj][2];
                sacc[nj][3] = __expf(sacc[nj][3] - mn1); l1 += sacc[nj][3];
            }
            m0 = mn0; m1 = mn1;

            uint32_t pah[4][4], pal[4][4];
            #pragma unroll
            for (int ks = 0; ks < 4; ks++) {
                pack_hl(sacc[2*ks][0],   sacc[2*ks][1],   pah[ks][0], pal[ks][0]);
                pack_hl(sacc[2*ks][2],   sacc[2*ks][3],   pah[ks][1], pal[ks][1]);
                pack_hl(sacc[2*ks+1][0], sacc[2*ks+1][1], pah[ks][2], pal[ks][2]);
                pack_hl(sacc[2*ks+1][2], sacc[2*ks+1][3], pah[ks][3], pal[ks][3]);
            }

            uint32_t vStage = stage + 8192;
            #pragma unroll
            for (int ks = 0; ks < 4; ks++) {
                #pragma unroll
                for (int nq = 0; nq < 4; nq++) {
                    uint32_t vh4[4];
                    ldm_x4_t(vh4, vStage + swz((uint32_t)((ks*16 + vRow) * 128 + nq*32 + vCb)));
                    mma16816(o[2*nq],   pah[ks], &vh4[0]);
                    mma16816(o[2*nq+1], pah[ks], &vh4[2]);
                    mma16816(o[2*nq],   pal[ks], &vh4[0]);
                    mma16816(o[2*nq+1], pal[ks], &vh4[2]);
                }
            }
        }

        __syncthreads();
        if (kt + 2 < nT) load_kv(sb + 32768 + (kt & 1) * 16384, bh, kt + 2, tid);
        cp_commit();
    }
    cp_wait0();

    l0 += __shfl_xor_sync(0xffffffffu, l0, 1);
    l0 += __shfl_xor_sync(0xffffffffu, l0, 2);
    l1 += __shfl_xor_sync(0xffffffffu, l1, 1);
    l1 += __shfl_xor_sync(0xffffffffu, l1, 2);
    float inv0 = 1.f / l0, inv1 = 1.f / l1;

    int b = bh >> 4, h = bh & 15;
    int row0 = qBase + w * 16 + (l >> 2);
    #pragma unroll
    for (int half = 0; half < 2; half++) {
        int row = row0 + half * 8;
        float inv = half ? inv1 : inv0;
        #pragma unroll
        for (int nj = 0; nj < 8; nj++) {
            int col = h * 64 + nj * 8 + (l & 3) * 2;
            float v0 = o[nj][half * 2 + 0] * inv;
            float v1 = o[nj][half * 2 + 1] * inv;
            uint32_t hh, ll;
            pack_hl(v0, v1, hh, ll);
            size_t gi = (size_t)(b * Sq + row) * Dm + col;
            *(uint32_t*)&g_ah[gi] = hh;
            *(uint32_t*)&g_al[gi] = ll;
        }
    }
}

// ---------------------------------------------------------------------------
extern "C" void kernel_launch(void* const* d_in, const int* in_sizes, int n_in,
                              void* d_out, int out_size)
{
    (void)in_sizes; (void)n_in; (void)out_size;
    const float* x  = (const float*)d_in[0];
    const float* w1 = (const float*)d_in[1];
    const float* b1 = (const float*)d_in[2];
    const float* w2 = (const float*)d_in[3];
    const float* b2 = (const float*)d_in[4];
    float* out = (float*)d_out;

    cudaFuncSetAttribute(tgemm<1>, cudaFuncAttributeMaxDynamicSharedMemorySize, SMEM_TOTAL2);
    cudaFuncSetAttribute(tgemm<0>, cudaFuncAttributeMaxDynamicSharedMemorySize, SMEM_TOTAL2);
    cudaFuncSetAttribute(flash_mma, cudaFuncAttributeMaxDynamicSharedMemorySize, FL_SMEM);

    split_k<<<4096, 256>>>(x, 4096 * 1024);
    tsplit_k<1><<<dim3(3072 / 32, 1024 / 32), dim3(32, 8)>>>(w1);
    tsplit_k<2><<<dim3(1024 / 32, 1024 / 32), dim3(32, 8)>>>(w2);

    tgemm<1><<<dim3(3072 / 128, 4096 / 256), 256, SMEM_TOTAL2>>>(b1, nullptr);
    flash_mma<<<512, 256, FL_SMEM>>>();
    tgemm<0><<<dim3(1024 / 128, 4096 / 256), 256, SMEM_TOTAL2>>>(b2, out);
}